// round 14
// baseline (speedup 1.0000x reference)
#include <cuda_runtime.h>
#include <math.h>
#include <stdint.h>

#define N_PRED 65536
#define N_GT   128
#define N_CLS  256
#define MAX_DYN 10
#define GEPS   1e-6f
#define IOU_THRES 0.25f
#define CAND_C 128      // per-row LSA candidates: exactly the 128 smallest
#define GCAP   8192     // per-gt qualifier list cap (global) and select sort cap
#define GC_NEED 1408    // per-gt dynamic candidate depth (10 + 128 + 10*127)
#define NBMW   (N_PRED/32)   // 2048 bitmap words
#define LSA_CAP 16512        // compact column universe cap; union <= 16384
#define SLOT_CAP 8192        // touched-column slots per augmentation
#define VV_CAP   2048        // nonzero-dual slots (persistent)

// dynamic smem layout for k_lsa
#define OFF_SLOT   0                         // u16[LSA_CAP]          33024
#define OFF_DIST   33024                     // f64[SLOT_CAP]         65536
#define OFF_PATH   98560                     // u8[SLOT_CAP]           8192
#define OFF_COL    106752                    // u16[SLOT_CAP]         16384
#define OFF_SC     123136                    // u32[SLOT_CAP/32]       1024
#define OFF_R      124160                    // u8[LSA_CAP]           16512
#define OFF_VSLOT  140672                    // u16[LSA_CAP]          33024
#define OFF_VVAL   173696                    // f64[VV_CAP]           16384
#define LSA_DYN_BYTES 190080

// dynamic smem for k_cost: gp1(2KB) + gp2(2KB) + sig_sh 128*129*4
#define COST_DYN_BYTES (4096 + 128*129*4)   // 70144
// dynamic smem for k_select: buf = GCAP ull
#define SEL_DYN_BYTES (GCAP * 8)            // 65536

typedef unsigned long long ull;

// ------------------- scratch (device globals; no runtime allocation) -------------------
__device__ float    d_costm[N_GT][N_PRED];  // 32MB  cost_T[g][p]
__device__ unsigned d_maxgk[N_GT];          // fkey(max giou) per gt (idempotent atomics)
__device__ int      d_gccnt[N_GT];          // qualifier counts (zeroed by k_select each run)
__device__ ull      d_glist[N_GT][GCAP];    // 8MB qualifier lists (key|pred)

__device__ int    d_ccand_idx[N_GT][CAND_C];  // orig col ids, sorted (cost,idx) asc
__device__ float  d_ccand_val[N_GT][CAND_C];
__device__ int    d_ccand_cnt[N_GT];
__device__ ull    d_ccpack[N_GT][CAND_C];     // (val_bits<<32)|compact_id

__device__ int    d_gcand_idx[N_GT][GC_NEED];
__device__ int    d_gcand_cnt[N_GT];

__device__ unsigned d_colbm[NBMW];
__device__ int    d_rev[N_PRED];          // compact id -> orig col

// monotonic ascending key for float
__device__ __forceinline__ unsigned fkey(float f) {
    unsigned u = __float_as_uint(f);
    return (u & 0x80000000u) ? ~u : (u | 0x80000000u);
}

// giou recompute (bit-identical to k_cost's op sequence)
__device__ __forceinline__ float giou_of(const float* __restrict__ pc,
                                         const float* __restrict__ ps, int p,
                                         float gl0, float gl1, float gl2,
                                         float gh0, float gh1, float gh2, float gvol) {
    float c0 = pc[p*3+0], c1 = pc[p*3+1], c2 = pc[p*3+2];
    float s0 = ps[p*3+0], s1 = ps[p*3+1], s2 = ps[p*3+2];
    float h0s = __fmul_rn(s0, 0.5f), h1s = __fmul_rn(s1, 0.5f), h2s = __fmul_rn(s2, 0.5f);
    float pl0 = __fsub_rn(c0, h0s), pl1 = __fsub_rn(c1, h1s), pl2 = __fsub_rn(c2, h2s);
    float ph0 = __fadd_rn(c0, h0s), ph1 = __fadd_rn(c1, h1s), ph2 = __fadd_rn(c2, h2s);
    float vol1 = __fmul_rn(__fmul_rn(__fsub_rn(ph0,pl0), __fsub_rn(ph1,pl1)), __fsub_rn(ph2,pl2));
    float d0 = fmaxf(__fsub_rn(fminf(ph0, gh0), fmaxf(pl0, gl0)), 0.f);
    float d1 = fmaxf(__fsub_rn(fminf(ph1, gh1), fmaxf(pl1, gl1)), 0.f);
    float d2 = fmaxf(__fsub_rn(fminf(ph2, gh2), fmaxf(pl2, gl2)), 0.f);
    float ov = __fmul_rn(__fmul_rn(d0, d1), d2);
    float un = fmaxf(__fsub_rn(__fadd_rn(vol1, gvol), ov), GEPS);
    float iou = __fdiv_rn(ov, un);
    float e0 = fmaxf(__fsub_rn(fmaxf(ph0, gh0), fminf(pl0, gl0)), 0.f);
    float e1 = fmaxf(__fsub_rn(fmaxf(ph1, gh1), fminf(pl1, gl1)), 0.f);
    float e2 = fmaxf(__fsub_rn(fmaxf(ph2, gh2), fminf(pl2, gl2)), 0.f);
    float enc = fmaxf(__fmul_rn(__fmul_rn(e0, e1), e2), GEPS);
    return __fsub_rn(iou, __fdiv_rn(__fsub_rn(enc, un), enc));
}

// block bitonic sort, ascending, n = power of two >= blockDim
__device__ __forceinline__ void bsort(ull* a, int n, int tid, int nth) {
    for (int k = 2; k <= n; k <<= 1) {
        for (int j = k >> 1; j > 0; j >>= 1) {
            for (int i = tid; i < n; i += nth) {
                int ixj = i ^ j;
                if (ixj > i) {
                    bool up = ((i & k) == 0);
                    ull x = a[i], y = a[ixj];
                    if ((x > y) == up) { a[i] = y; a[ixj] = x; }
                }
            }
            __syncthreads();
        }
    }
}

// ------------------- cost matrix + fused giou collection -------------------
__global__ void k_cost(const float* __restrict__ pc, const float* __restrict__ ps,
                       const float* __restrict__ cls,
                       const float* __restrict__ gc, const float* __restrict__ gs,
                       const void* __restrict__ lab) {
    extern __shared__ unsigned char csm[];
    float4* gp1 = (float4*)csm;                  // lo0, lo1, lo2, gvol
    float4* gp2 = (float4*)(csm + 2048);         // hi0, hi1, hi2, (unused)
    float*  sig_sh = (float*)(csm + 4096);       // [g*129 + p_local], conflict-free
    __shared__ int glab[N_GT];
    __shared__ unsigned maxsh[N_GT];
    __shared__ int is32;
    int tid = threadIdx.x;  // blockDim = 512
    int lane = tid & 31;
    if (blockIdx.x == 0) {
        for (int i = tid; i < NBMW; i += blockDim.x) d_colbm[i] = 0u;
    }
    if (tid == 0) {
        const ull* p8 = (const ull*)lab;
        int f = 0;
        for (int i = 0; i < 64; i++) { if (p8[i] >> 32) { f = 1; break; } }
        is32 = f;
    }
    __syncthreads();
    if (tid < N_GT) {
        int t = tid;
        maxsh[t] = 0u;
        long long lv;
        if (is32) lv = (long long)((const int*)lab)[t];
        else      lv = ((const long long*)lab)[t];
        int iv = (int)lv;
        if (iv < 0) iv = 0;
        if (iv >= N_CLS) iv = N_CLS - 1;
        glab[t] = iv;
        float c0 = gc[t*3+0], c1 = gc[t*3+1], c2 = gc[t*3+2];
        float s0 = gs[t*3+0], s1 = gs[t*3+1], s2 = gs[t*3+2];
        float h0s = __fmul_rn(s0, 0.5f), h1s = __fmul_rn(s1, 0.5f), h2s = __fmul_rn(s2, 0.5f);
        float l0 = __fsub_rn(c0, h0s), l1 = __fsub_rn(c1, h1s), l2 = __fsub_rn(c2, h2s);
        float h0 = __fadd_rn(c0, h0s), h1 = __fadd_rn(c1, h1s), h2 = __fadd_rn(c2, h2s);
        float gv = __fmul_rn(__fmul_rn(__fsub_rn(h0,l0), __fsub_rn(h1,l1)), __fsub_rn(h2,l2));
        gp1[t] = make_float4(l0, l1, l2, gv);
        gp2[t] = make_float4(h0, h1, h2, 0.0f);
    }
    __syncthreads();

    // ---- phase A: warp-cooperative sigmoid staging ----
    {
        int w = tid >> 5;
        for (int pl_ = w; pl_ < 128; pl_ += 16) {
            const float* clsrow = cls + ((size_t)(blockIdx.x * 128 + pl_)) * N_CLS;
            #pragma unroll
            for (int q = 0; q < 4; q++) {
                int g = lane + q * 32;
                float cv = __ldg(clsrow + glab[g]);
                float sig = __fdiv_rn(1.0f, __fadd_rn(1.0f, expf(-cv)));
                sig_sh[g * 129 + pl_] = sig;
            }
        }
    }
    __syncthreads();

    // ---- phase B: matrix + collection ----
    int pl = tid & 127;
    int p = blockIdx.x * 128 + pl;
    int gbase = (tid >> 7) * 32;
    float c0 = pc[p*3+0], c1 = pc[p*3+1], c2 = pc[p*3+2];
    float s0 = ps[p*3+0], s1 = ps[p*3+1], s2 = ps[p*3+2];
    float h0s = __fmul_rn(s0, 0.5f), h1s = __fmul_rn(s1, 0.5f), h2s = __fmul_rn(s2, 0.5f);
    float pl0 = __fsub_rn(c0, h0s), pl1 = __fsub_rn(c1, h1s), pl2 = __fsub_rn(c2, h2s);
    float ph0 = __fadd_rn(c0, h0s), ph1 = __fadd_rn(c1, h1s), ph2 = __fadd_rn(c2, h2s);
    float vol1 = __fmul_rn(__fmul_rn(__fsub_rn(ph0,pl0), __fsub_rn(ph1,pl1)), __fsub_rn(ph2,pl2));

    #pragma unroll 4
    for (int gi_ = 0; gi_ < 32; gi_++) {
        int g = gbase + gi_;
        float4 A = gp1[g];
        float4 B = gp2[g];
        float d0 = fmaxf(__fsub_rn(fminf(ph0, B.x), fmaxf(pl0, A.x)), 0.f);
        float d1 = fmaxf(__fsub_rn(fminf(ph1, B.y), fmaxf(pl1, A.y)), 0.f);
        float d2 = fmaxf(__fsub_rn(fminf(ph2, B.z), fmaxf(pl2, A.z)), 0.f);
        float ov = __fmul_rn(__fmul_rn(d0, d1), d2);
        float un = fmaxf(__fsub_rn(__fadd_rn(vol1, A.w), ov), GEPS);
        float iou = __fdiv_rn(ov, un);
        float e0 = fmaxf(__fsub_rn(fmaxf(ph0, B.x), fminf(pl0, A.x)), 0.f);
        float e1 = fmaxf(__fsub_rn(fmaxf(ph1, B.y), fminf(pl1, A.y)), 0.f);
        float e2 = fmaxf(__fsub_rn(fmaxf(ph2, B.z), fminf(pl2, A.z)), 0.f);
        float enc = fmaxf(__fmul_rn(__fmul_rn(e0, e1), e2), GEPS);
        float gg = __fsub_rn(iou, __fdiv_rn(__fsub_rn(enc, un), enc));
        float sig = sig_sh[g * 129 + pl];
        d_costm[g][p] = __fadd_rn(-sig, __fmul_rn(-2.0f, gg));

        // per-g warp max (all lanes share g)
        unsigned mk = fkey(gg);
        unsigned wm = __reduce_max_sync(0xffffffffu, mk);
        if (lane == 0) atomicMax(&maxsh[g], wm);

        // warp-aggregated qualifier collection (sparse)
        bool q = gg > IOU_THRES;
        unsigned mask = __ballot_sync(0xffffffffu, q);
        if (mask) {
            int leader = __ffs(mask) - 1;
            int base = 0;
            if (lane == leader) base = atomicAdd(&d_gccnt[g], __popc(mask));
            base = __shfl_sync(0xffffffffu, base, leader);
            if (q) {
                int pos = base + __popc(mask & ((1u << lane) - 1u));
                if (pos < GCAP)
                    d_glist[g][pos] = ((ull)(~fkey(gg)) << 32) | (unsigned)p;
            }
        }
    }
    __syncthreads();
    if (tid < N_GT) atomicMax(&d_maxgk[tid], maxsh[tid]);
}

// ------------------- selection -------------------
// blocks 0..127: cost rows (scan+sample+sort); 128..255: giou rows (list or recompute)
__global__ void k_select(const float* __restrict__ pc, const float* __restrict__ ps,
                         const float* __restrict__ gc, const float* __restrict__ gs) {
    extern __shared__ unsigned char ssm[];
    ull* buf = (ull*)ssm;            // GCAP entries (64KB); aliased as hist in fallbacks
    __shared__ ull samp[512];
    __shared__ int s_cnt, s_c;

    int b = blockIdx.x, tid = threadIdx.x, nth = blockDim.x;  // nth = 512
    unsigned* hist = (unsigned*)buf;

    if (b < N_GT) {
        // ================= cost row =================
        int row = b;
        const float* crow = d_costm[row];
        const float4* crow4 = (const float4*)crow;
        if (tid < 512) {
            float v = crow[tid * 128];
            samp[tid] = ((ull)fkey(v) << 32) | (unsigned)(tid * 128);
        }
        __syncthreads();
        bsort(samp, 512, tid, nth);

        const int slist[5] = {4, 16, 64, 255, 511};
        int si = 0, cc = 0, truecnt = 0;
        while (true) {
            if (tid == 0) s_cnt = 0;
            __syncthreads();
            unsigned Tkey = (unsigned)(samp[slist[si]] >> 32);
            for (int j4 = tid; j4 < N_PRED / 4; j4 += nth) {
                float4 v4 = crow4[j4];
                int j = j4 * 4;
                unsigned k0 = fkey(v4.x), k1 = fkey(v4.y), k2 = fkey(v4.z), k3 = fkey(v4.w);
                if (k0 <= Tkey) { int s = atomicAdd(&s_cnt, 1); if (s < GCAP) buf[s] = ((ull)k0 << 32) | (unsigned)(j+0); }
                if (k1 <= Tkey) { int s = atomicAdd(&s_cnt, 1); if (s < GCAP) buf[s] = ((ull)k1 << 32) | (unsigned)(j+1); }
                if (k2 <= Tkey) { int s = atomicAdd(&s_cnt, 1); if (s < GCAP) buf[s] = ((ull)k2 << 32) | (unsigned)(j+2); }
                if (k3 <= Tkey) { int s = atomicAdd(&s_cnt, 1); if (s < GCAP) buf[s] = ((ull)k3 << 32) | (unsigned)(j+3); }
            }
            __syncthreads();
            truecnt = s_cnt;
            cc = (truecnt < GCAP) ? truecnt : GCAP;
            if (truecnt >= CAND_C && truecnt <= GCAP) break;
            if (truecnt > GCAP) {
                // rare: tie-heavy. exact 2-level 2048-bin histogram.
                for (int i = tid; i < 2048; i += nth) hist[i] = 0;
                __syncthreads();
                for (int j = tid; j < N_PRED; j += nth)
                    atomicAdd(&hist[fkey(crow[j]) >> 21], 1u);
                __syncthreads();
                if (tid == 0) {
                    unsigned need = CAND_C, cum = 0; int bb = 0;
                    for (; bb < 2047; bb++) { if (cum + hist[bb] >= need) break; cum += hist[bb]; }
                    s_c = bb; s_cnt = (int)(need - cum);
                }
                __syncthreads();
                unsigned pfx11 = (unsigned)s_c; int need1 = s_cnt;
                __syncthreads();
                for (int i = tid; i < 2048; i += nth) hist[i] = 0;
                __syncthreads();
                for (int j = tid; j < N_PRED; j += nth) {
                    unsigned k = fkey(crow[j]);
                    if ((k >> 21) == pfx11) atomicAdd(&hist[(k >> 10) & 2047u], 1u);
                }
                __syncthreads();
                if (tid == 0) {
                    unsigned need = (unsigned)need1, cum = 0; int bb = 0;
                    for (; bb < 2047; bb++) { if (cum + hist[bb] >= need) break; cum += hist[bb]; }
                    s_c = (int)((pfx11 << 11) | (unsigned)bb);
                    s_cnt = 0;
                }
                __syncthreads();
                unsigned pfx22 = (unsigned)s_c;
                __syncthreads();
                for (int j = tid; j < N_PRED; j += nth) {
                    unsigned k = fkey(crow[j]);
                    if ((k >> 10) <= pfx22) {
                        int slot = atomicAdd(&s_cnt, 1);
                        if (slot < GCAP) buf[slot] = ((ull)k << 32) | (unsigned)j;
                    }
                }
                __syncthreads();
                truecnt = s_cnt;
                cc = (truecnt < GCAP) ? truecnt : GCAP;
                break;
            }
            si++;
            if (si >= 5) break;
            __syncthreads();
        }
        int n2 = 512; while (n2 < cc) n2 <<= 1;
        for (int i = tid + cc; i < n2; i += nth) buf[i] = 0xFFFFFFFFFFFFFFFFull;
        __syncthreads();
        bsort(buf, n2, tid, nth);
        int keep = (cc < CAND_C) ? cc : CAND_C;
        for (int i = tid; i < keep; i += nth) {
            ull e = buf[i];
            int j = (int)(e & 0xFFFFFFFFull);
            d_ccand_idx[row][i] = j;
            d_ccand_val[row][i] = crow[j];
            atomicOr(&d_colbm[j >> 5], 1u << (j & 31));
        }
        if (tid == 0) d_ccand_cnt[row] = keep;
    } else {
        // ================= giou row =================
        int row = b - N_GT;
        int count = d_gccnt[row];
        int cc;
        if (count <= GCAP) {
            // list path: load collected qualifiers
            const ull* gl = d_glist[row];
            for (int i = tid; i < count; i += nth) buf[i] = gl[i];
            cc = count;
        } else {
            // rare fallback: recompute giou row exactly, exact histogram top-GC_NEED
            float gcx0 = gc[row*3+0], gcx1 = gc[row*3+1], gcx2 = gc[row*3+2];
            float gsx0 = gs[row*3+0], gsx1 = gs[row*3+1], gsx2 = gs[row*3+2];
            float gh0s = __fmul_rn(gsx0,0.5f), gh1s = __fmul_rn(gsx1,0.5f), gh2s = __fmul_rn(gsx2,0.5f);
            float gl0 = __fsub_rn(gcx0,gh0s), gl1 = __fsub_rn(gcx1,gh1s), gl2 = __fsub_rn(gcx2,gh2s);
            float gh0 = __fadd_rn(gcx0,gh0s), gh1 = __fadd_rn(gcx1,gh1s), gh2 = __fadd_rn(gcx2,gh2s);
            float gvol = __fmul_rn(__fmul_rn(__fsub_rn(gh0,gl0), __fsub_rn(gh1,gl1)), __fsub_rn(gh2,gl2));

            for (int i = tid; i < 2048; i += nth) hist[i] = 0;
            __syncthreads();
            for (int j = tid; j < N_PRED; j += nth) {
                float g = giou_of(pc, ps, j, gl0, gl1, gl2, gh0, gh1, gh2, gvol);
                if (g > IOU_THRES) atomicAdd(&hist[(~fkey(g)) >> 21], 1u);
            }
            __syncthreads();
            if (tid == 0) {
                unsigned need = GC_NEED, cum = 0; int bb = 0;
                for (; bb < 2047; bb++) { if (cum + hist[bb] >= need) break; cum += hist[bb]; }
                s_c = bb; s_cnt = (int)(need - cum);
            }
            __syncthreads();
            unsigned pfx11 = (unsigned)s_c; int need1 = s_cnt;
            __syncthreads();
            for (int i = tid; i < 2048; i += nth) hist[i] = 0;
            __syncthreads();
            for (int j = tid; j < N_PRED; j += nth) {
                float g = giou_of(pc, ps, j, gl0, gl1, gl2, gh0, gh1, gh2, gvol);
                if (g > IOU_THRES) {
                    unsigned k = ~fkey(g);
                    if ((k >> 21) == pfx11) atomicAdd(&hist[(k >> 10) & 2047u], 1u);
                }
            }
            __syncthreads();
            if (tid == 0) {
                unsigned need = (unsigned)need1, cum = 0; int bb = 0;
                for (; bb < 2047; bb++) { if (cum + hist[bb] >= need) break; cum += hist[bb]; }
                s_c = (int)((pfx11 << 11) | (unsigned)bb);
                s_cnt = 0;
            }
            __syncthreads();
            unsigned pfx22 = (unsigned)s_c;
            __syncthreads();
            for (int j = tid; j < N_PRED; j += nth) {
                float g = giou_of(pc, ps, j, gl0, gl1, gl2, gh0, gh1, gh2, gvol);
                if (!(g > IOU_THRES)) continue;
                unsigned k = ~fkey(g);
                if ((k >> 10) <= pfx22) {
                    int slot = atomicAdd(&s_cnt, 1);
                    if (slot < GCAP) buf[slot] = ((ull)k << 32) | (unsigned)j;
                }
            }
            __syncthreads();
            cc = (s_cnt < GCAP) ? s_cnt : GCAP;
        }
        __syncthreads();
        int n2 = 512; while (n2 < cc) n2 <<= 1;
        for (int i = tid + cc; i < n2; i += nth) buf[i] = 0xFFFFFFFFFFFFFFFFull;
        __syncthreads();
        bsort(buf, n2, tid, nth);   // key asc == giou desc, idx asc
        int cnt = (cc < GC_NEED) ? cc : GC_NEED;
        for (int i = tid; i < cnt; i += nth)
            d_gcand_idx[row][i] = (int)(buf[i] & 0xFFFFFFFFull);
        if (tid == 0) {
            d_gcand_cnt[row] = cnt;
            d_gccnt[row] = 0;   // reset counter for next graph replay
        }
    }
}

// ------------------- LSA (slot-based smem state) + dynamic assign + output -----------
__global__ void k_lsa(float* __restrict__ out) {
    extern __shared__ unsigned char dsm[];
    uint16_t* shSlot = (uint16_t*)(dsm + OFF_SLOT);   // cid -> slot (0xFFFF = untouched)
    double*   sDist  = (double*)(dsm + OFF_DIST);
    uint8_t*  sPath  = (uint8_t*)(dsm + OFF_PATH);
    uint16_t* sCol   = (uint16_t*)(dsm + OFF_COL);    // slot -> cid
    unsigned* sSC    = (unsigned*)(dsm + OFF_SC);     // per-slot SC bits
    uint8_t*  shR    = (uint8_t*)(dsm + OFF_R);       // cid -> row (255 = free)
    uint16_t* vslot  = (uint16_t*)(dsm + OFF_VSLOT);  // cid -> v slot (0xFFFF = v==0)
    double*   vval   = (double*)(dsm + OFF_VVAL);
    int*      cbase  = (int*)(dsm + OFF_SLOT);        // alias during prologue only

    __shared__ double u[N_GT];
    __shared__ int SR[N_GT];
    __shared__ int c4r[N_GT];
    __shared__ int pend[N_GT];
    __shared__ int scnt[N_GT];
    __shared__ float s0val[N_GT];
    __shared__ int   s0idx[N_GT];
    __shared__ int   colro[N_GT];
    __shared__ double rv[8];
    __shared__ int rc[8];
    __shared__ int tsum[256];
    __shared__ int s_row, s_sink, s_tcnt, s_vcnt, s_npend, s_nSR;
    __shared__ double s_minval;

    int tid = threadIdx.x, nth = blockDim.x;  // 256
    const double DINF = 1e300;

    // ---- compact scan of column bitmap (cbase aliases shSlot region) ----
    int wbase = tid * 8;
    int cnts8[8]; int ssum = 0;
    #pragma unroll
    for (int w = 0; w < 8; w++) { cnts8[w] = __popc(d_colbm[wbase + w]); ssum += cnts8[w]; }
    tsum[tid] = ssum;
    __syncthreads();
    for (int off = 1; off < 256; off <<= 1) {
        int v_ = 0;
        if (tid >= off) v_ = tsum[tid - off];
        __syncthreads();
        tsum[tid] += v_;
        __syncthreads();
    }
    int excl = tsum[tid] - ssum;
    #pragma unroll
    for (int w = 0; w < 8; w++) { cbase[wbase + w] = excl; excl += cnts8[w]; }
    __syncthreads();
    int nK = tsum[255];
    if (nK > LSA_CAP) nK = LSA_CAP;   // impossible (union <= 16384), safety only

    // ---- remap: build packed (val|cid) candidates + reverse map ----
    for (int x = tid; x < N_GT * CAND_C; x += nth) {
        int row = x >> 7, s = x & 127;
        if (s < d_ccand_cnt[row]) {
            int j = d_ccand_idx[row][s];
            int w = j >> 5;
            int cid = cbase[w] + __popc(d_colbm[w] & ((1u << (j & 31)) - 1u));
            float v_ = d_ccand_val[row][s];
            d_ccpack[row][s] = ((ull)__float_as_uint(v_) << 32) | (unsigned)cid;
            d_rev[cid] = j;
        }
    }
    __syncthreads();   // cbase dead; shSlot region free

    // ---- init smem state ----
    {
        unsigned* p32 = (unsigned*)shSlot;
        for (int i = tid; i < LSA_CAP/2; i += nth) p32[i] = 0xFFFFFFFFu;
        unsigned* q32 = (unsigned*)vslot;
        for (int i = tid; i < LSA_CAP/2; i += nth) q32[i] = 0xFFFFFFFFu;
    }
    for (int i = tid; i < nK; i += nth) shR[i] = 0xFF;
    for (int i = tid; i < SLOT_CAP/32; i += nth) sSC[i] = 0;
    if (tid < N_GT) {
        c4r[tid] = -1;
        scnt[tid] = d_ccand_cnt[tid];
        ull pk = d_ccpack[tid][0];
        s0idx[tid] = (int)(pk & 0xFFFFFFFFull);
        s0val[tid] = __uint_as_float((unsigned)(pk >> 32));
    }
    if (tid == 0) s_vcnt = 0;
    __syncthreads();

    // ---- greedy tight assignment (pure smem, serial) ----
    if (tid == 0) {
        s_npend = 0;
        for (int i = 0; i < N_GT; i++) {
            if (scnt[i] > 0) {
                u[i] = (double)s0val[i];
                int j = s0idx[i];
                if (j >= 0 && j < nK && shR[j] == 0xFF) {
                    shR[j] = (uint8_t)i; c4r[i] = j;
                    continue;
                }
            } else u[i] = 0.0;
            pend[s_npend++] = i;
        }
    }
    __syncthreads();
    int npend = s_npend;

    // ---- block-wide shortest augmenting path per conflicted row ----
    for (int pi = 0; pi < npend; pi++) {
        int cur = pend[pi];
        if (tid == 0) { s_row = cur; s_sink = -1; s_tcnt = 0; s_nSR = 0; s_minval = 0.0; }
        __syncthreads();
        for (int step = 0; step < N_GT; step++) {
            int i = s_row;
            if (tid == 0) SR[s_nSR++] = i;
            double mv0 = s_minval, ui = u[i];
            int cnt = scnt[i];
            for (int s = tid; s < cnt; s += nth) {
                ull pk = d_ccpack[i][s];
                int cid = (int)(pk & 0xFFFFFFFFull);
                int slot = shSlot[cid];
                if (slot != 0xFFFF && ((sSC[slot >> 5] >> (slot & 31)) & 1u)) continue;
                int vs = vslot[cid];
                double v_ = (vs != 0xFFFF) ? vval[vs] : 0.0;
                double r = ((mv0 + (double)__uint_as_float((unsigned)(pk >> 32))) - ui) - v_;
                if (slot == 0xFFFF) {
                    int t2 = atomicAdd(&s_tcnt, 1);
                    if (t2 < SLOT_CAP) {
                        shSlot[cid] = (uint16_t)t2;
                        sCol[t2] = (uint16_t)cid;
                        sDist[t2] = r;
                        sPath[t2] = (uint8_t)i;
                    }
                } else if (r < sDist[slot]) {
                    sDist[slot] = r; sPath[slot] = (uint8_t)i;
                }
            }
            __syncthreads();
            int tcnt = s_tcnt; if (tcnt > SLOT_CAP) tcnt = SLOT_CAP;
            double bv = DINF; int bc = 0x7fffffff;
            for (int t2 = tid; t2 < tcnt; t2 += nth) {
                if ((sSC[t2 >> 5] >> (t2 & 31)) & 1u) continue;
                double sv = sDist[t2];
                int cid = sCol[t2];
                if (sv < bv || (sv == bv && cid < bc)) { bv = sv; bc = cid; }
            }
            #pragma unroll
            for (int off = 16; off > 0; off >>= 1) {
                double ov = __shfl_down_sync(0xffffffffu, bv, off);
                int   oc = __shfl_down_sync(0xffffffffu, bc, off);
                if (ov < bv || (ov == bv && oc < bc)) { bv = ov; bc = oc; }
            }
            if ((tid & 31) == 0) { rv[tid >> 5] = bv; rc[tid >> 5] = bc; }
            __syncthreads();
            if (tid == 0) {
                double fbv = rv[0]; int fbc = rc[0];
                #pragma unroll
                for (int k = 1; k < 8; k++) {
                    if (rv[k] < fbv || (rv[k] == fbv && rc[k] < fbc)) { fbv = rv[k]; fbc = rc[k]; }
                }
                if (fbc >= 0 && fbc < nK) {
                    s_minval = fbv;
                    int slot = shSlot[fbc];
                    sSC[slot >> 5] |= (1u << (slot & 31));
                    int r4 = shR[fbc];
                    if (r4 == 0xFF) s_sink = fbc; else s_row = r4;
                } else s_sink = -2;
            }
            __syncthreads();
            if (s_sink != -1) break;
        }
        if (s_sink >= 0) {
            double mv = s_minval;
            if (tid == 0) {
                u[cur] += mv;
                for (int k = 1; k < s_nSR; k++) {
                    int i2 = SR[k];
                    u[i2] += mv - sDist[shSlot[c4r[i2]]];
                }
            }
            int tcnt = s_tcnt; if (tcnt > SLOT_CAP) tcnt = SLOT_CAP;
            for (int t2 = tid; t2 < tcnt; t2 += nth) {
                if ((sSC[t2 >> 5] >> (t2 & 31)) & 1u) {
                    int cid = sCol[t2];
                    int vs = vslot[cid];
                    if (vs == 0xFFFF) {
                        vs = atomicAdd(&s_vcnt, 1);
                        if (vs < VV_CAP) { vslot[cid] = (uint16_t)vs; vval[vs] = 0.0; }
                    }
                    if (vs < VV_CAP) vval[vs] -= mv - sDist[t2];
                }
            }
            __syncthreads();
            if (tid == 0) {
                int j = s_sink;
                for (int it = 0; it <= N_GT && j >= 0; it++) {
                    int i2 = sPath[shSlot[j]];
                    shR[j] = (uint8_t)i2;
                    int tmp = c4r[i2];
                    c4r[i2] = j;
                    j = tmp;
                    if (i2 == cur) break;
                }
            }
        }
        __syncthreads();
        // reset only the touched entries
        {
            int tw = (s_tcnt < SLOT_CAP ? s_tcnt : SLOT_CAP);
            for (int t2 = tid; t2 < tw; t2 += nth) shSlot[sCol[t2]] = 0xFFFF;
            for (int i = tid; i < (tw + 31) / 32; i += nth) sSC[i] = 0;
        }
        __syncthreads();
    }
    if (tid < N_GT) colro[tid] = (c4r[tid] >= 0) ? d_rev[c4r[tid]] : -1;
    __syncthreads();

    // ================= dynamic assignment phase (reuses dead dsm region) =================
    unsigned* used = (unsigned*)dsm;                    // 8KB @ 0
    int* res_p = (int*)(dsm + 8192);                    // 5632B
    int* res_g = (int*)(dsm + 13824);                   // 5632B
    int* pref  = (int*)(dsm + 19456);                   // 16KB: pref[g*32+s], depth 32
    int* gcnts = (int*)(dsm + 35840);                   // 512B
    int* ordv  = (int*)(dsm + 36352);                   // 512B
    unsigned* mgk = (unsigned*)(dsm + 36864);           // 512B

    for (int i = tid; i < NBMW; i += nth) used[i] = 0;
    if (tid < N_GT) { gcnts[tid] = d_gcand_cnt[tid]; mgk[tid] = d_maxgk[tid]; }
    __syncthreads();
    // stable ascending argsort of maxg keys (fkey monotonic => same order as floats)
    if (tid < N_GT) {
        unsigned mv = mgk[tid]; int r = 0;
        for (int j = 0; j < N_GT; j++) {
            unsigned o = mgk[j];
            if (o < mv || (o == mv && j < tid)) r++;
        }
        ordv[r] = tid;
    }
    for (int i = tid; i < N_GT * 32; i += nth) {
        int g = i >> 5, s = i & 31;
        pref[i] = (s < gcnts[g]) ? d_gcand_idx[g][s] : -1;
    }
    if (tid < N_GT) {
        int p = colro[tid];
        if (p >= 0 && p < N_PRED) atomicOr(&used[p >> 5], 1u << (p & 31));
        res_p[tid] = p;
        res_g[tid] = tid;
    }
    __syncthreads();
    if (tid < 32) {
        int lane = tid;
        for (int t = 0; t < N_GT; t++) {
            int g = ordv[t];
            int cnt = gcnts[g];
            int picked = 0;
            for (int base = 0; base < cnt && picked < MAX_DYN; base += 32) {
                int idx = -1;
                if (base + lane < cnt)
                    idx = (base == 0) ? pref[g * 32 + lane] : d_gcand_idx[g][base + lane];
                bool elig = (idx >= 0) && (idx < N_PRED) && !((used[idx >> 5] >> (idx & 31)) & 1u);
                unsigned m = __ballot_sync(0xffffffffu, elig);
                int K = MAX_DYN - picked;
                int pre = __popc(m & ((1u << lane) - 1u));
                if (elig && pre < K) {
                    atomicOr(&used[idx >> 5], 1u << (idx & 31));
                    res_p[128 + t * MAX_DYN + picked + pre] = idx;
                    res_g[128 + t * MAX_DYN + picked + pre] = g;
                }
                int got = __popc(m); if (got > K) got = K;
                picked += got;
                __syncwarp();
            }
            if (lane >= picked && lane < MAX_DYN) {
                res_p[128 + t * MAX_DYN + lane] = -1;
                res_g[128 + t * MAX_DYN + lane] = -1;
            }
            __syncwarp();
        }
    }
    __syncthreads();
    for (int i = tid; i < 1408; i += nth) {
        out[i]        = (float)res_p[i];
        out[1408 + i] = (float)res_g[i];
    }
}

// ------------------- launch (inputs resolved by element count) -------------------
extern "C" void kernel_launch(void* const* d_in, const int* in_sizes, int n_in,
                              void* d_out, int out_size) {
    const float* all_centers = 0;
    const float* all_sizes   = 0;
    const float* all_cls     = 0;
    const float* gt_centers  = 0;
    const float* gt_sizes    = 0;
    const void*  gt_labels   = 0;
    int seen196 = 0, seen384 = 0;
    for (int i = 0; i < n_in; i++) {
        long long s = in_sizes[i];
        if (s == (long long)N_PRED * N_CLS) {
            all_cls = (const float*)d_in[i];
        } else if (s == (long long)N_PRED * 3) {
            if (seen196++ == 0) all_centers = (const float*)d_in[i];
            else                all_sizes   = (const float*)d_in[i];
        } else if (s == (long long)N_GT * 3) {
            if (seen384++ == 0) gt_centers = (const float*)d_in[i];
            else                gt_sizes   = (const float*)d_in[i];
        } else if (s == (long long)N_GT) {
            gt_labels = d_in[i];
        }
    }

    cudaFuncSetAttribute(k_cost, cudaFuncAttributeMaxDynamicSharedMemorySize, COST_DYN_BYTES);
    cudaFuncSetAttribute(k_select, cudaFuncAttributeMaxDynamicSharedMemorySize, SEL_DYN_BYTES);
    cudaFuncSetAttribute(k_lsa, cudaFuncAttributeMaxDynamicSharedMemorySize, LSA_DYN_BYTES);

    k_cost<<<N_PRED / 128, 512, COST_DYN_BYTES>>>(all_centers, all_sizes, all_cls,
                                                  gt_centers, gt_sizes, gt_labels);
    k_select<<<2 * N_GT, 512, SEL_DYN_BYTES>>>(all_centers, all_sizes, gt_centers, gt_sizes);
    k_lsa<<<1, 256, LSA_DYN_BYTES>>>((float*)d_out);
}

// round 15
// speedup vs baseline: 1.0327x; 1.0327x over previous
#include <cuda_runtime.h>
#include <math.h>
#include <stdint.h>

#define N_PRED 65536
#define N_GT   128
#define N_CLS  256
#define MAX_DYN 10
#define GEPS   1e-6f
#define IOU_THRES 0.25f
#define CAND_C 128      // per-row LSA candidates: exactly the 128 smallest
#define GCAP   8192     // per-gt qualifier list cap (global) and select sort cap
#define GC_NEED 1408    // per-gt dynamic candidate depth (10 + 128 + 10*127)
#define NBMW   (N_PRED/32)   // 2048 bitmap words
#define LSA_CAP 16512        // compact column universe cap; union <= 16384
#define SLOT_CAP 8192        // touched-column slots per augmentation
#define VV_CAP   2048        // nonzero-dual slots (persistent)

// dynamic smem layout for k_lsa
#define OFF_SLOT   0                         // u16[LSA_CAP]          33024
#define OFF_DIST   33024                     // f64[SLOT_CAP]         65536
#define OFF_PATH   98560                     // u8[SLOT_CAP]           8192
#define OFF_COL    106752                    // u16[SLOT_CAP]         16384
#define OFF_SC     123136                    // u32[SLOT_CAP/32]       1024
#define OFF_R      124160                    // u8[LSA_CAP]           16512
#define OFF_VSLOT  140672                    // u16[LSA_CAP]          33024
#define OFF_VVAL   173696                    // f64[VV_CAP]           16384
#define LSA_DYN_BYTES 190080

// dynamic smem for k_cost: gp1(2KB) + gp2(2KB) + sig_sh 128*129*4
#define COST_DYN_BYTES (4096 + 128*129*4)   // 70144
// dynamic smem for k_select: buf = GCAP ull
#define SEL_DYN_BYTES (GCAP * 8)            // 65536

typedef unsigned long long ull;

// ------------------- scratch (device globals; no runtime allocation) -------------------
__device__ float    d_costm[N_GT][N_PRED];  // 32MB  cost_T[g][p]
__device__ unsigned d_maxgk[N_GT];          // fkey(max giou) per gt (written by k_select)
__device__ int      d_gccnt[N_GT];          // qualifier counts (zeroed by k_select each run)
__device__ ull      d_glist[N_GT][GCAP];    // 8MB qualifier lists (key|pred)

__device__ int    d_ccand_idx[N_GT][CAND_C];  // orig col ids, sorted (cost,idx) asc
__device__ float  d_ccand_val[N_GT][CAND_C];
__device__ int    d_ccand_cnt[N_GT];
__device__ ull    d_ccpack[N_GT][CAND_C];     // (val_bits<<32)|compact_id

__device__ int    d_gcand_idx[N_GT][GC_NEED];
__device__ int    d_gcand_cnt[N_GT];

__device__ unsigned d_colbm[NBMW];
__device__ int    d_rev[N_PRED];          // compact id -> orig col

// monotonic ascending key for float
__device__ __forceinline__ unsigned fkey(float f) {
    unsigned u = __float_as_uint(f);
    return (u & 0x80000000u) ? ~u : (u | 0x80000000u);
}

// giou recompute (bit-identical to k_cost's op sequence)
__device__ __forceinline__ float giou_of(const float* __restrict__ pc,
                                         const float* __restrict__ ps, int p,
                                         float gl0, float gl1, float gl2,
                                         float gh0, float gh1, float gh2, float gvol) {
    float c0 = pc[p*3+0], c1 = pc[p*3+1], c2 = pc[p*3+2];
    float s0 = ps[p*3+0], s1 = ps[p*3+1], s2 = ps[p*3+2];
    float h0s = __fmul_rn(s0, 0.5f), h1s = __fmul_rn(s1, 0.5f), h2s = __fmul_rn(s2, 0.5f);
    float pl0 = __fsub_rn(c0, h0s), pl1 = __fsub_rn(c1, h1s), pl2 = __fsub_rn(c2, h2s);
    float ph0 = __fadd_rn(c0, h0s), ph1 = __fadd_rn(c1, h1s), ph2 = __fadd_rn(c2, h2s);
    float vol1 = __fmul_rn(__fmul_rn(__fsub_rn(ph0,pl0), __fsub_rn(ph1,pl1)), __fsub_rn(ph2,pl2));
    float d0 = fmaxf(__fsub_rn(fminf(ph0, gh0), fmaxf(pl0, gl0)), 0.f);
    float d1 = fmaxf(__fsub_rn(fminf(ph1, gh1), fmaxf(pl1, gl1)), 0.f);
    float d2 = fmaxf(__fsub_rn(fminf(ph2, gh2), fmaxf(pl2, gl2)), 0.f);
    float ov = __fmul_rn(__fmul_rn(d0, d1), d2);
    float un = fmaxf(__fsub_rn(__fadd_rn(vol1, gvol), ov), GEPS);
    float iou = __fdiv_rn(ov, un);
    float e0 = fmaxf(__fsub_rn(fmaxf(ph0, gh0), fminf(pl0, gl0)), 0.f);
    float e1 = fmaxf(__fsub_rn(fmaxf(ph1, gh1), fminf(pl1, gl1)), 0.f);
    float e2 = fmaxf(__fsub_rn(fmaxf(ph2, gh2), fminf(pl2, gl2)), 0.f);
    float enc = fmaxf(__fmul_rn(__fmul_rn(e0, e1), e2), GEPS);
    return __fsub_rn(iou, __fdiv_rn(__fsub_rn(enc, un), enc));
}

// block bitonic sort, ascending, n = power of two >= blockDim
__device__ __forceinline__ void bsort(ull* a, int n, int tid, int nth) {
    for (int k = 2; k <= n; k <<= 1) {
        for (int j = k >> 1; j > 0; j >>= 1) {
            for (int i = tid; i < n; i += nth) {
                int ixj = i ^ j;
                if (ixj > i) {
                    bool up = ((i & k) == 0);
                    ull x = a[i], y = a[ixj];
                    if ((x > y) == up) { a[i] = y; a[ixj] = x; }
                }
            }
            __syncthreads();
        }
    }
}

// ------------------- cost matrix + fused giou qualifier collection -------------------
__global__ void __launch_bounds__(512, 3)
k_cost(const float* __restrict__ pc, const float* __restrict__ ps,
       const float* __restrict__ cls,
       const float* __restrict__ gc, const float* __restrict__ gs,
       const void* __restrict__ lab) {
    extern __shared__ unsigned char csm[];
    float4* gp1 = (float4*)csm;                  // lo0, lo1, lo2, gvol
    float4* gp2 = (float4*)(csm + 2048);         // hi0, hi1, hi2, (unused)
    float*  sig_sh = (float*)(csm + 4096);       // [g*129 + p_local], conflict-free
    __shared__ int glab[N_GT];
    __shared__ int is32;
    int tid = threadIdx.x;  // blockDim = 512
    int lane = tid & 31;
    if (blockIdx.x == 0) {
        for (int i = tid; i < NBMW; i += blockDim.x) d_colbm[i] = 0u;
    }
    if (tid == 0) {
        const ull* p8 = (const ull*)lab;
        int f = 0;
        for (int i = 0; i < 64; i++) { if (p8[i] >> 32) { f = 1; break; } }
        is32 = f;
    }
    __syncthreads();
    if (tid < N_GT) {
        int t = tid;
        long long lv;
        if (is32) lv = (long long)((const int*)lab)[t];
        else      lv = ((const long long*)lab)[t];
        int iv = (int)lv;
        if (iv < 0) iv = 0;
        if (iv >= N_CLS) iv = N_CLS - 1;
        glab[t] = iv;
        float c0 = gc[t*3+0], c1 = gc[t*3+1], c2 = gc[t*3+2];
        float s0 = gs[t*3+0], s1 = gs[t*3+1], s2 = gs[t*3+2];
        float h0s = __fmul_rn(s0, 0.5f), h1s = __fmul_rn(s1, 0.5f), h2s = __fmul_rn(s2, 0.5f);
        float l0 = __fsub_rn(c0, h0s), l1 = __fsub_rn(c1, h1s), l2 = __fsub_rn(c2, h2s);
        float h0 = __fadd_rn(c0, h0s), h1 = __fadd_rn(c1, h1s), h2 = __fadd_rn(c2, h2s);
        float gv = __fmul_rn(__fmul_rn(__fsub_rn(h0,l0), __fsub_rn(h1,l1)), __fsub_rn(h2,l2));
        gp1[t] = make_float4(l0, l1, l2, gv);
        gp2[t] = make_float4(h0, h1, h2, 0.0f);
    }
    __syncthreads();

    // ---- phase A: warp-cooperative sigmoid staging ----
    {
        int w = tid >> 5;
        for (int pl_ = w; pl_ < 128; pl_ += 16) {
            const float* clsrow = cls + ((size_t)(blockIdx.x * 128 + pl_)) * N_CLS;
            #pragma unroll
            for (int q = 0; q < 4; q++) {
                int g = lane + q * 32;
                float cv = __ldg(clsrow + glab[g]);
                float sig = __fdiv_rn(1.0f, __fadd_rn(1.0f, expf(-cv)));
                sig_sh[g * 129 + pl_] = sig;
            }
        }
    }
    __syncthreads();

    // ---- phase B: matrix + qualifier collection ----
    int pl = tid & 127;
    int p = blockIdx.x * 128 + pl;
    int gbase = (tid >> 7) * 32;
    float c0 = pc[p*3+0], c1 = pc[p*3+1], c2 = pc[p*3+2];
    float s0 = ps[p*3+0], s1 = ps[p*3+1], s2 = ps[p*3+2];
    float h0s = __fmul_rn(s0, 0.5f), h1s = __fmul_rn(s1, 0.5f), h2s = __fmul_rn(s2, 0.5f);
    float pl0 = __fsub_rn(c0, h0s), pl1 = __fsub_rn(c1, h1s), pl2 = __fsub_rn(c2, h2s);
    float ph0 = __fadd_rn(c0, h0s), ph1 = __fadd_rn(c1, h1s), ph2 = __fadd_rn(c2, h2s);
    float vol1 = __fmul_rn(__fmul_rn(__fsub_rn(ph0,pl0), __fsub_rn(ph1,pl1)), __fsub_rn(ph2,pl2));

    #pragma unroll 4
    for (int gi_ = 0; gi_ < 32; gi_++) {
        int g = gbase + gi_;
        float4 A = gp1[g];
        float4 B = gp2[g];
        float d0 = fmaxf(__fsub_rn(fminf(ph0, B.x), fmaxf(pl0, A.x)), 0.f);
        float d1 = fmaxf(__fsub_rn(fminf(ph1, B.y), fmaxf(pl1, A.y)), 0.f);
        float d2 = fmaxf(__fsub_rn(fminf(ph2, B.z), fmaxf(pl2, A.z)), 0.f);
        float ov = __fmul_rn(__fmul_rn(d0, d1), d2);
        float un = fmaxf(__fsub_rn(__fadd_rn(vol1, A.w), ov), GEPS);
        float iou = __fdiv_rn(ov, un);
        float e0 = fmaxf(__fsub_rn(fmaxf(ph0, B.x), fminf(pl0, A.x)), 0.f);
        float e1 = fmaxf(__fsub_rn(fmaxf(ph1, B.y), fminf(pl1, A.y)), 0.f);
        float e2 = fmaxf(__fsub_rn(fmaxf(ph2, B.z), fminf(pl2, A.z)), 0.f);
        float enc = fmaxf(__fmul_rn(__fmul_rn(e0, e1), e2), GEPS);
        float gg = __fsub_rn(iou, __fdiv_rn(__fsub_rn(enc, un), enc));
        float sig = sig_sh[g * 129 + pl];
        d_costm[g][p] = __fadd_rn(-sig, __fmul_rn(-2.0f, gg));

        // warp-aggregated qualifier collection (sparse; ~2 instrs when empty)
        bool q = gg > IOU_THRES;
        unsigned mask = __ballot_sync(0xffffffffu, q);
        if (mask) {
            int leader = __ffs(mask) - 1;
            int base = 0;
            if (lane == leader) base = atomicAdd(&d_gccnt[g], __popc(mask));
            base = __shfl_sync(0xffffffffu, base, leader);
            if (q) {
                int pos = base + __popc(mask & ((1u << lane) - 1u));
                if (pos < GCAP)
                    d_glist[g][pos] = ((ull)(~fkey(gg)) << 32) | (unsigned)p;
            }
        }
    }
}

// ------------------- selection -------------------
// blocks 0..127: cost rows (scan+sample+sort); 128..255: giou rows (list or recompute)
__global__ void k_select(const float* __restrict__ pc, const float* __restrict__ ps,
                         const float* __restrict__ gc, const float* __restrict__ gs) {
    extern __shared__ unsigned char ssm[];
    ull* buf = (ull*)ssm;            // GCAP entries (64KB); aliased as hist in fallbacks
    __shared__ ull samp[512];
    __shared__ int s_cnt, s_c;

    int b = blockIdx.x, tid = threadIdx.x, nth = blockDim.x;  // nth = 512
    unsigned* hist = (unsigned*)buf;

    if (b < N_GT) {
        // ================= cost row =================
        int row = b;
        const float* crow = d_costm[row];
        const float4* crow4 = (const float4*)crow;
        if (tid < 512) {
            float v = crow[tid * 128];
            samp[tid] = ((ull)fkey(v) << 32) | (unsigned)(tid * 128);
        }
        __syncthreads();
        bsort(samp, 512, tid, nth);

        const int slist[5] = {4, 16, 64, 255, 511};
        int si = 0, cc = 0, truecnt = 0;
        while (true) {
            if (tid == 0) s_cnt = 0;
            __syncthreads();
            unsigned Tkey = (unsigned)(samp[slist[si]] >> 32);
            for (int j4 = tid; j4 < N_PRED / 4; j4 += nth) {
                float4 v4 = crow4[j4];
                int j = j4 * 4;
                unsigned k0 = fkey(v4.x), k1 = fkey(v4.y), k2 = fkey(v4.z), k3 = fkey(v4.w);
                if (k0 <= Tkey) { int s = atomicAdd(&s_cnt, 1); if (s < GCAP) buf[s] = ((ull)k0 << 32) | (unsigned)(j+0); }
                if (k1 <= Tkey) { int s = atomicAdd(&s_cnt, 1); if (s < GCAP) buf[s] = ((ull)k1 << 32) | (unsigned)(j+1); }
                if (k2 <= Tkey) { int s = atomicAdd(&s_cnt, 1); if (s < GCAP) buf[s] = ((ull)k2 << 32) | (unsigned)(j+2); }
                if (k3 <= Tkey) { int s = atomicAdd(&s_cnt, 1); if (s < GCAP) buf[s] = ((ull)k3 << 32) | (unsigned)(j+3); }
            }
            __syncthreads();
            truecnt = s_cnt;
            cc = (truecnt < GCAP) ? truecnt : GCAP;
            if (truecnt >= CAND_C && truecnt <= GCAP) break;
            if (truecnt > GCAP) {
                // rare: tie-heavy. exact 2-level 2048-bin histogram.
                for (int i = tid; i < 2048; i += nth) hist[i] = 0;
                __syncthreads();
                for (int j = tid; j < N_PRED; j += nth)
                    atomicAdd(&hist[fkey(crow[j]) >> 21], 1u);
                __syncthreads();
                if (tid == 0) {
                    unsigned need = CAND_C, cum = 0; int bb = 0;
                    for (; bb < 2047; bb++) { if (cum + hist[bb] >= need) break; cum += hist[bb]; }
                    s_c = bb; s_cnt = (int)(need - cum);
                }
                __syncthreads();
                unsigned pfx11 = (unsigned)s_c; int need1 = s_cnt;
                __syncthreads();
                for (int i = tid; i < 2048; i += nth) hist[i] = 0;
                __syncthreads();
                for (int j = tid; j < N_PRED; j += nth) {
                    unsigned k = fkey(crow[j]);
                    if ((k >> 21) == pfx11) atomicAdd(&hist[(k >> 10) & 2047u], 1u);
                }
                __syncthreads();
                if (tid == 0) {
                    unsigned need = (unsigned)need1, cum = 0; int bb = 0;
                    for (; bb < 2047; bb++) { if (cum + hist[bb] >= need) break; cum += hist[bb]; }
                    s_c = (int)((pfx11 << 11) | (unsigned)bb);
                    s_cnt = 0;
                }
                __syncthreads();
                unsigned pfx22 = (unsigned)s_c;
                __syncthreads();
                for (int j = tid; j < N_PRED; j += nth) {
                    unsigned k = fkey(crow[j]);
                    if ((k >> 10) <= pfx22) {
                        int slot = atomicAdd(&s_cnt, 1);
                        if (slot < GCAP) buf[slot] = ((ull)k << 32) | (unsigned)j;
                    }
                }
                __syncthreads();
                truecnt = s_cnt;
                cc = (truecnt < GCAP) ? truecnt : GCAP;
                break;
            }
            si++;
            if (si >= 5) break;
            __syncthreads();
        }
        int n2 = 512; while (n2 < cc) n2 <<= 1;
        for (int i = tid + cc; i < n2; i += nth) buf[i] = 0xFFFFFFFFFFFFFFFFull;
        __syncthreads();
        bsort(buf, n2, tid, nth);
        int keep = (cc < CAND_C) ? cc : CAND_C;
        for (int i = tid; i < keep; i += nth) {
            ull e = buf[i];
            int j = (int)(e & 0xFFFFFFFFull);
            d_ccand_idx[row][i] = j;
            d_ccand_val[row][i] = crow[j];
            atomicOr(&d_colbm[j >> 5], 1u << (j & 31));
        }
        if (tid == 0) d_ccand_cnt[row] = keep;
    } else {
        // ================= giou row =================
        int row = b - N_GT;
        int count = d_gccnt[row];
        int cc;
        if (count <= GCAP) {
            // list path: load collected qualifiers
            const ull* gl = d_glist[row];
            for (int i = tid; i < count; i += nth) buf[i] = gl[i];
            cc = count;
        } else {
            // rare fallback: recompute giou row exactly, exact histogram top-GC_NEED
            float gcx0 = gc[row*3+0], gcx1 = gc[row*3+1], gcx2 = gc[row*3+2];
            float gsx0 = gs[row*3+0], gsx1 = gs[row*3+1], gsx2 = gs[row*3+2];
            float gh0s = __fmul_rn(gsx0,0.5f), gh1s = __fmul_rn(gsx1,0.5f), gh2s = __fmul_rn(gsx2,0.5f);
            float gl0 = __fsub_rn(gcx0,gh0s), gl1 = __fsub_rn(gcx1,gh1s), gl2 = __fsub_rn(gcx2,gh2s);
            float gh0 = __fadd_rn(gcx0,gh0s), gh1 = __fadd_rn(gcx1,gh1s), gh2 = __fadd_rn(gcx2,gh2s);
            float gvol = __fmul_rn(__fmul_rn(__fsub_rn(gh0,gl0), __fsub_rn(gh1,gl1)), __fsub_rn(gh2,gl2));

            for (int i = tid; i < 2048; i += nth) hist[i] = 0;
            __syncthreads();
            for (int j = tid; j < N_PRED; j += nth) {
                float g = giou_of(pc, ps, j, gl0, gl1, gl2, gh0, gh1, gh2, gvol);
                if (g > IOU_THRES) atomicAdd(&hist[(~fkey(g)) >> 21], 1u);
            }
            __syncthreads();
            if (tid == 0) {
                unsigned need = GC_NEED, cum = 0; int bb = 0;
                for (; bb < 2047; bb++) { if (cum + hist[bb] >= need) break; cum += hist[bb]; }
                s_c = bb; s_cnt = (int)(need - cum);
            }
            __syncthreads();
            unsigned pfx11 = (unsigned)s_c; int need1 = s_cnt;
            __syncthreads();
            for (int i = tid; i < 2048; i += nth) hist[i] = 0;
            __syncthreads();
            for (int j = tid; j < N_PRED; j += nth) {
                float g = giou_of(pc, ps, j, gl0, gl1, gl2, gh0, gh1, gh2, gvol);
                if (g > IOU_THRES) {
                    unsigned k = ~fkey(g);
                    if ((k >> 21) == pfx11) atomicAdd(&hist[(k >> 10) & 2047u], 1u);
                }
            }
            __syncthreads();
            if (tid == 0) {
                unsigned need = (unsigned)need1, cum = 0; int bb = 0;
                for (; bb < 2047; bb++) { if (cum + hist[bb] >= need) break; cum += hist[bb]; }
                s_c = (int)((pfx11 << 11) | (unsigned)bb);
                s_cnt = 0;
            }
            __syncthreads();
            unsigned pfx22 = (unsigned)s_c;
            __syncthreads();
            for (int j = tid; j < N_PRED; j += nth) {
                float g = giou_of(pc, ps, j, gl0, gl1, gl2, gh0, gh1, gh2, gvol);
                if (!(g > IOU_THRES)) continue;
                unsigned k = ~fkey(g);
                if ((k >> 10) <= pfx22) {
                    int slot = atomicAdd(&s_cnt, 1);
                    if (slot < GCAP) buf[slot] = ((ull)k << 32) | (unsigned)j;
                }
            }
            __syncthreads();
            cc = (s_cnt < GCAP) ? s_cnt : GCAP;
        }
        __syncthreads();
        int n2 = 512; while (n2 < cc) n2 <<= 1;
        for (int i = tid + cc; i < n2; i += nth) buf[i] = 0xFFFFFFFFFFFFFFFFull;
        __syncthreads();
        bsort(buf, n2, tid, nth);   // key asc == giou desc, idx asc
        int cnt = (cc < GC_NEED) ? cc : GC_NEED;
        for (int i = tid; i < cnt; i += nth)
            d_gcand_idx[row][i] = (int)(buf[i] & 0xFFFFFFFFull);
        if (tid == 0) {
            d_gcand_cnt[row] = cnt;
            d_gccnt[row] = 0;   // reset counter for next graph replay
            // row max = first sorted qualifier (max > thres iff cc>0); else key 0
            // (zero-qualifier gts sort first in ANY internal order; their output
            //  rows are all (-1,-1) so the permutation among them is invariant)
            d_maxgk[row] = (cc > 0) ? ~((unsigned)(buf[0] >> 32)) : 0u;
        }
    }
}

// ------------------- LSA (slot-based smem state) + dynamic assign + output -----------
__global__ void k_lsa(float* __restrict__ out) {
    extern __shared__ unsigned char dsm[];
    uint16_t* shSlot = (uint16_t*)(dsm + OFF_SLOT);   // cid -> slot (0xFFFF = untouched)
    double*   sDist  = (double*)(dsm + OFF_DIST);
    uint8_t*  sPath  = (uint8_t*)(dsm + OFF_PATH);
    uint16_t* sCol   = (uint16_t*)(dsm + OFF_COL);    // slot -> cid
    unsigned* sSC    = (unsigned*)(dsm + OFF_SC);     // per-slot SC bits
    uint8_t*  shR    = (uint8_t*)(dsm + OFF_R);       // cid -> row (255 = free)
    uint16_t* vslot  = (uint16_t*)(dsm + OFF_VSLOT);  // cid -> v slot (0xFFFF = v==0)
    double*   vval   = (double*)(dsm + OFF_VVAL);
    int*      cbase  = (int*)(dsm + OFF_SLOT);        // alias during prologue only

    __shared__ double u[N_GT];
    __shared__ int SR[N_GT];
    __shared__ int c4r[N_GT];
    __shared__ int pend[N_GT];
    __shared__ int scnt[N_GT];
    __shared__ float s0val[N_GT];
    __shared__ int   s0idx[N_GT];
    __shared__ int   colro[N_GT];
    __shared__ double rv[8];
    __shared__ int rc[8];
    __shared__ int tsum[256];
    __shared__ int s_row, s_sink, s_tcnt, s_vcnt, s_npend, s_nSR;
    __shared__ double s_minval;

    int tid = threadIdx.x, nth = blockDim.x;  // 256
    const double DINF = 1e300;

    // ---- compact scan of column bitmap (cbase aliases shSlot region) ----
    int wbase = tid * 8;
    int cnts8[8]; int ssum = 0;
    #pragma unroll
    for (int w = 0; w < 8; w++) { cnts8[w] = __popc(d_colbm[wbase + w]); ssum += cnts8[w]; }
    tsum[tid] = ssum;
    __syncthreads();
    for (int off = 1; off < 256; off <<= 1) {
        int v_ = 0;
        if (tid >= off) v_ = tsum[tid - off];
        __syncthreads();
        tsum[tid] += v_;
        __syncthreads();
    }
    int excl = tsum[tid] - ssum;
    #pragma unroll
    for (int w = 0; w < 8; w++) { cbase[wbase + w] = excl; excl += cnts8[w]; }
    __syncthreads();
    int nK = tsum[255];
    if (nK > LSA_CAP) nK = LSA_CAP;   // impossible (union <= 16384), safety only

    // ---- remap: build packed (val|cid) candidates + reverse map ----
    for (int x = tid; x < N_GT * CAND_C; x += nth) {
        int row = x >> 7, s = x & 127;
        if (s < d_ccand_cnt[row]) {
            int j = d_ccand_idx[row][s];
            int w = j >> 5;
            int cid = cbase[w] + __popc(d_colbm[w] & ((1u << (j & 31)) - 1u));
            float v_ = d_ccand_val[row][s];
            d_ccpack[row][s] = ((ull)__float_as_uint(v_) << 32) | (unsigned)cid;
            d_rev[cid] = j;
        }
    }
    __syncthreads();   // cbase dead; shSlot region free

    // ---- init smem state ----
    {
        unsigned* p32 = (unsigned*)shSlot;
        for (int i = tid; i < LSA_CAP/2; i += nth) p32[i] = 0xFFFFFFFFu;
        unsigned* q32 = (unsigned*)vslot;
        for (int i = tid; i < LSA_CAP/2; i += nth) q32[i] = 0xFFFFFFFFu;
    }
    for (int i = tid; i < nK; i += nth) shR[i] = 0xFF;
    for (int i = tid; i < SLOT_CAP/32; i += nth) sSC[i] = 0;
    if (tid < N_GT) {
        c4r[tid] = -1;
        scnt[tid] = d_ccand_cnt[tid];
        ull pk = d_ccpack[tid][0];
        s0idx[tid] = (int)(pk & 0xFFFFFFFFull);
        s0val[tid] = __uint_as_float((unsigned)(pk >> 32));
    }
    if (tid == 0) s_vcnt = 0;
    __syncthreads();

    // ---- greedy tight assignment (pure smem, serial) ----
    if (tid == 0) {
        s_npend = 0;
        for (int i = 0; i < N_GT; i++) {
            if (scnt[i] > 0) {
                u[i] = (double)s0val[i];
                int j = s0idx[i];
                if (j >= 0 && j < nK && shR[j] == 0xFF) {
                    shR[j] = (uint8_t)i; c4r[i] = j;
                    continue;
                }
            } else u[i] = 0.0;
            pend[s_npend++] = i;
        }
    }
    __syncthreads();
    int npend = s_npend;

    // ---- block-wide shortest augmenting path per conflicted row ----
    for (int pi = 0; pi < npend; pi++) {
        int cur = pend[pi];
        if (tid == 0) { s_row = cur; s_sink = -1; s_tcnt = 0; s_nSR = 0; s_minval = 0.0; }
        __syncthreads();
        for (int step = 0; step < N_GT; step++) {
            int i = s_row;
            if (tid == 0) SR[s_nSR++] = i;
            double mv0 = s_minval, ui = u[i];
            int cnt = scnt[i];
            for (int s = tid; s < cnt; s += nth) {
                ull pk = d_ccpack[i][s];
                int cid = (int)(pk & 0xFFFFFFFFull);
                int slot = shSlot[cid];
                if (slot != 0xFFFF && ((sSC[slot >> 5] >> (slot & 31)) & 1u)) continue;
                int vs = vslot[cid];
                double v_ = (vs != 0xFFFF) ? vval[vs] : 0.0;
                double r = ((mv0 + (double)__uint_as_float((unsigned)(pk >> 32))) - ui) - v_;
                if (slot == 0xFFFF) {
                    int t2 = atomicAdd(&s_tcnt, 1);
                    if (t2 < SLOT_CAP) {
                        shSlot[cid] = (uint16_t)t2;
                        sCol[t2] = (uint16_t)cid;
                        sDist[t2] = r;
                        sPath[t2] = (uint8_t)i;
                    }
                } else if (r < sDist[slot]) {
                    sDist[slot] = r; sPath[slot] = (uint8_t)i;
                }
            }
            __syncthreads();
            int tcnt = s_tcnt; if (tcnt > SLOT_CAP) tcnt = SLOT_CAP;
            double bv = DINF; int bc = 0x7fffffff;
            for (int t2 = tid; t2 < tcnt; t2 += nth) {
                if ((sSC[t2 >> 5] >> (t2 & 31)) & 1u) continue;
                double sv = sDist[t2];
                int cid = sCol[t2];
                if (sv < bv || (sv == bv && cid < bc)) { bv = sv; bc = cid; }
            }
            #pragma unroll
            for (int off = 16; off > 0; off >>= 1) {
                double ov = __shfl_down_sync(0xffffffffu, bv, off);
                int   oc = __shfl_down_sync(0xffffffffu, bc, off);
                if (ov < bv || (ov == bv && oc < bc)) { bv = ov; bc = oc; }
            }
            if ((tid & 31) == 0) { rv[tid >> 5] = bv; rc[tid >> 5] = bc; }
            __syncthreads();
            if (tid == 0) {
                double fbv = rv[0]; int fbc = rc[0];
                #pragma unroll
                for (int k = 1; k < 8; k++) {
                    if (rv[k] < fbv || (rv[k] == fbv && rc[k] < fbc)) { fbv = rv[k]; fbc = rc[k]; }
                }
                if (fbc >= 0 && fbc < nK) {
                    s_minval = fbv;
                    int slot = shSlot[fbc];
                    sSC[slot >> 5] |= (1u << (slot & 31));
                    int r4 = shR[fbc];
                    if (r4 == 0xFF) s_sink = fbc; else s_row = r4;
                } else s_sink = -2;
            }
            __syncthreads();
            if (s_sink != -1) break;
        }
        if (s_sink >= 0) {
            double mv = s_minval;
            if (tid == 0) {
                u[cur] += mv;
                for (int k = 1; k < s_nSR; k++) {
                    int i2 = SR[k];
                    u[i2] += mv - sDist[shSlot[c4r[i2]]];
                }
            }
            int tcnt = s_tcnt; if (tcnt > SLOT_CAP) tcnt = SLOT_CAP;
            for (int t2 = tid; t2 < tcnt; t2 += nth) {
                if ((sSC[t2 >> 5] >> (t2 & 31)) & 1u) {
                    int cid = sCol[t2];
                    int vs = vslot[cid];
                    if (vs == 0xFFFF) {
                        vs = atomicAdd(&s_vcnt, 1);
                        if (vs < VV_CAP) { vslot[cid] = (uint16_t)vs; vval[vs] = 0.0; }
                    }
                    if (vs < VV_CAP) vval[vs] -= mv - sDist[t2];
                }
            }
            __syncthreads();
            if (tid == 0) {
                int j = s_sink;
                for (int it = 0; it <= N_GT && j >= 0; it++) {
                    int i2 = sPath[shSlot[j]];
                    shR[j] = (uint8_t)i2;
                    int tmp = c4r[i2];
                    c4r[i2] = j;
                    j = tmp;
                    if (i2 == cur) break;
                }
            }
        }
        __syncthreads();
        // reset only the touched entries
        {
            int tw = (s_tcnt < SLOT_CAP ? s_tcnt : SLOT_CAP);
            for (int t2 = tid; t2 < tw; t2 += nth) shSlot[sCol[t2]] = 0xFFFF;
            for (int i = tid; i < (tw + 31) / 32; i += nth) sSC[i] = 0;
        }
        __syncthreads();
    }
    if (tid < N_GT) colro[tid] = (c4r[tid] >= 0) ? d_rev[c4r[tid]] : -1;
    __syncthreads();

    // ================= dynamic assignment phase (reuses dead dsm region) =================
    unsigned* used = (unsigned*)dsm;                    // 8KB @ 0
    int* res_p = (int*)(dsm + 8192);                    // 5632B
    int* res_g = (int*)(dsm + 13824);                   // 5632B
    int* pref  = (int*)(dsm + 19456);                   // 16KB: pref[g*32+s], depth 32
    int* gcnts = (int*)(dsm + 35840);                   // 512B
    int* ordv  = (int*)(dsm + 36352);                   // 512B
    unsigned* mgk = (unsigned*)(dsm + 36864);           // 512B

    for (int i = tid; i < NBMW; i += nth) used[i] = 0;
    if (tid < N_GT) { gcnts[tid] = d_gcand_cnt[tid]; mgk[tid] = d_maxgk[tid]; }
    __syncthreads();
    // stable ascending argsort of maxg keys (fkey monotonic => same order as floats)
    if (tid < N_GT) {
        unsigned mv = mgk[tid]; int r = 0;
        for (int j = 0; j < N_GT; j++) {
            unsigned o = mgk[j];
            if (o < mv || (o == mv && j < tid)) r++;
        }
        ordv[r] = tid;
    }
    for (int i = tid; i < N_GT * 32; i += nth) {
        int g = i >> 5, s = i & 31;
        pref[i] = (s < gcnts[g]) ? d_gcand_idx[g][s] : -1;
    }
    if (tid < N_GT) {
        int p = colro[tid];
        if (p >= 0 && p < N_PRED) atomicOr(&used[p >> 5], 1u << (p & 31));
        res_p[tid] = p;
        res_g[tid] = tid;
    }
    __syncthreads();
    if (tid < 32) {
        int lane = tid;
        for (int t = 0; t < N_GT; t++) {
            int g = ordv[t];
            int cnt = gcnts[g];
            int picked = 0;
            for (int base = 0; base < cnt && picked < MAX_DYN; base += 32) {
                int idx = -1;
                if (base + lane < cnt)
                    idx = (base == 0) ? pref[g * 32 + lane] : d_gcand_idx[g][base + lane];
                bool elig = (idx >= 0) && (idx < N_PRED) && !((used[idx >> 5] >> (idx & 31)) & 1u);
                unsigned m = __ballot_sync(0xffffffffu, elig);
                int K = MAX_DYN - picked;
                int pre = __popc(m & ((1u << lane) - 1u));
                if (elig && pre < K) {
                    atomicOr(&used[idx >> 5], 1u << (idx & 31));
                    res_p[128 + t * MAX_DYN + picked + pre] = idx;
                    res_g[128 + t * MAX_DYN + picked + pre] = g;
                }
                int got = __popc(m); if (got > K) got = K;
                picked += got;
                __syncwarp();
            }
            if (lane >= picked && lane < MAX_DYN) {
                res_p[128 + t * MAX_DYN + lane] = -1;
                res_g[128 + t * MAX_DYN + lane] = -1;
            }
            __syncwarp();
        }
    }
    __syncthreads();
    for (int i = tid; i < 1408; i += nth) {
        out[i]        = (float)res_p[i];
        out[1408 + i] = (float)res_g[i];
    }
}

// ------------------- launch (inputs resolved by element count) -------------------
extern "C" void kernel_launch(void* const* d_in, const int* in_sizes, int n_in,
                              void* d_out, int out_size) {
    const float* all_centers = 0;
    const float* all_sizes   = 0;
    const float* all_cls     = 0;
    const float* gt_centers  = 0;
    const float* gt_sizes    = 0;
    const void*  gt_labels   = 0;
    int seen196 = 0, seen384 = 0;
    for (int i = 0; i < n_in; i++) {
        long long s = in_sizes[i];
        if (s == (long long)N_PRED * N_CLS) {
            all_cls = (const float*)d_in[i];
        } else if (s == (long long)N_PRED * 3) {
            if (seen196++ == 0) all_centers = (const float*)d_in[i];
            else                all_sizes   = (const float*)d_in[i];
        } else if (s == (long long)N_GT * 3) {
            if (seen384++ == 0) gt_centers = (const float*)d_in[i];
            else                gt_sizes   = (const float*)d_in[i];
        } else if (s == (long long)N_GT) {
            gt_labels = d_in[i];
        }
    }

    cudaFuncSetAttribute(k_cost, cudaFuncAttributeMaxDynamicSharedMemorySize, COST_DYN_BYTES);
    cudaFuncSetAttribute(k_select, cudaFuncAttributeMaxDynamicSharedMemorySize, SEL_DYN_BYTES);
    cudaFuncSetAttribute(k_lsa, cudaFuncAttributeMaxDynamicSharedMemorySize, LSA_DYN_BYTES);

    k_cost<<<N_PRED / 128, 512, COST_DYN_BYTES>>>(all_centers, all_sizes, all_cls,
                                                  gt_centers, gt_sizes, gt_labels);
    k_select<<<2 * N_GT, 512, SEL_DYN_BYTES>>>(all_centers, all_sizes, gt_centers, gt_sizes);
    k_lsa<<<1, 256, LSA_DYN_BYTES>>>((float*)d_out);
}

// round 16
// speedup vs baseline: 1.0479x; 1.0148x over previous
#include <cuda_runtime.h>
#include <math.h>
#include <stdint.h>

#define N_PRED 65536
#define N_GT   128
#define N_CLS  256
#define MAX_DYN 10
#define GEPS   1e-6f
#define IOU_THRES 0.25f
#define CAND_C 128      // per-row LSA candidates: exactly the 128 smallest
#define GCAP   8192     // per-gt qualifier list cap (global) and select sort cap
#define GC_NEED 1408    // per-gt dynamic candidate depth (10 + 128 + 10*127)
#define NBMW   (N_PRED/32)   // 2048 bitmap words
#define LSA_CAP 16512        // compact column universe cap; union <= 16384
#define SLOT_CAP 8192        // touched-column slots per augmentation
#define VV_CAP   2048        // nonzero-dual slots (persistent)

// dynamic smem layout for k_lsa
#define OFF_SLOT   0                         // u16[LSA_CAP]          33024
#define OFF_DIST   33024                     // f64[SLOT_CAP]         65536
#define OFF_PATH   98560                     // u8[SLOT_CAP]           8192
#define OFF_COL    106752                    // u16[SLOT_CAP]         16384
#define OFF_SC     123136                    // u32[SLOT_CAP/32]       1024
#define OFF_R      124160                    // u8[LSA_CAP]           16512
#define OFF_VSLOT  140672                    // u16[LSA_CAP]          33024
#define OFF_VVAL   173696                    // f64[VV_CAP]           16384
#define LSA_DYN_BYTES 190080

// k_cost: 32 preds/block. gp1(2KB) + gp2(2KB) + sig_sh 128*33*4
#define COST_PREDS 32
#define COST_DYN_BYTES (4096 + 128*33*4)    // 20992
// dynamic smem for k_select: buf = GCAP ull
#define SEL_DYN_BYTES (GCAP * 8)            // 65536

typedef unsigned long long ull;

// ------------------- scratch (device globals; no runtime allocation) -------------------
__device__ float    d_costm[N_GT][N_PRED];  // 32MB  cost_T[g][p]
__device__ unsigned d_maxgk[N_GT];          // fkey(max giou) per gt (written by k_select)
__device__ int      d_gccnt[N_GT];          // qualifier counts (zeroed by k_select each run)
__device__ ull      d_glist[N_GT][GCAP];    // 8MB qualifier lists (key|pred)

__device__ int    d_ccand_idx[N_GT][CAND_C];  // orig col ids, sorted (cost,idx) asc
__device__ float  d_ccand_val[N_GT][CAND_C];
__device__ int    d_ccand_cnt[N_GT];
__device__ ull    d_ccpack[N_GT][CAND_C];     // (val_bits<<32)|compact_id

__device__ int    d_gcand_idx[N_GT][GC_NEED];
__device__ int    d_gcand_cnt[N_GT];

__device__ unsigned d_colbm[NBMW];
__device__ int    d_rev[N_PRED];          // compact id -> orig col

// monotonic ascending key for float
__device__ __forceinline__ unsigned fkey(float f) {
    unsigned u = __float_as_uint(f);
    return (u & 0x80000000u) ? ~u : (u | 0x80000000u);
}

// giou recompute (bit-identical to k_cost's op sequence)
__device__ __forceinline__ float giou_of(const float* __restrict__ pc,
                                         const float* __restrict__ ps, int p,
                                         float gl0, float gl1, float gl2,
                                         float gh0, float gh1, float gh2, float gvol) {
    float c0 = pc[p*3+0], c1 = pc[p*3+1], c2 = pc[p*3+2];
    float s0 = ps[p*3+0], s1 = ps[p*3+1], s2 = ps[p*3+2];
    float h0s = __fmul_rn(s0, 0.5f), h1s = __fmul_rn(s1, 0.5f), h2s = __fmul_rn(s2, 0.5f);
    float pl0 = __fsub_rn(c0, h0s), pl1 = __fsub_rn(c1, h1s), pl2 = __fsub_rn(c2, h2s);
    float ph0 = __fadd_rn(c0, h0s), ph1 = __fadd_rn(c1, h1s), ph2 = __fadd_rn(c2, h2s);
    float vol1 = __fmul_rn(__fmul_rn(__fsub_rn(ph0,pl0), __fsub_rn(ph1,pl1)), __fsub_rn(ph2,pl2));
    float d0 = fmaxf(__fsub_rn(fminf(ph0, gh0), fmaxf(pl0, gl0)), 0.f);
    float d1 = fmaxf(__fsub_rn(fminf(ph1, gh1), fmaxf(pl1, gl1)), 0.f);
    float d2 = fmaxf(__fsub_rn(fminf(ph2, gh2), fmaxf(pl2, gl2)), 0.f);
    float ov = __fmul_rn(__fmul_rn(d0, d1), d2);
    float un = fmaxf(__fsub_rn(__fadd_rn(vol1, gvol), ov), GEPS);
    float iou = __fdiv_rn(ov, un);
    // e >= 0 always (boxes have hi >= lo); clip(…,0) is a bit-identical no-op
    float e0 = __fsub_rn(fmaxf(ph0, gh0), fminf(pl0, gl0));
    float e1 = __fsub_rn(fmaxf(ph1, gh1), fminf(pl1, gl1));
    float e2 = __fsub_rn(fmaxf(ph2, gh2), fminf(pl2, gl2));
    float enc = fmaxf(__fmul_rn(__fmul_rn(e0, e1), e2), GEPS);
    return __fsub_rn(iou, __fdiv_rn(__fsub_rn(enc, un), enc));
}

// block bitonic sort, ascending, n = power of two >= blockDim
__device__ __forceinline__ void bsort(ull* a, int n, int tid, int nth) {
    for (int k = 2; k <= n; k <<= 1) {
        for (int j = k >> 1; j > 0; j >>= 1) {
            for (int i = tid; i < n; i += nth) {
                int ixj = i ^ j;
                if (ixj > i) {
                    bool up = ((i & k) == 0);
                    ull x = a[i], y = a[ixj];
                    if ((x > y) == up) { a[i] = y; a[ixj] = x; }
                }
            }
            __syncthreads();
        }
    }
}

// ------------------- cost matrix + fused giou qualifier collection -------------------
// 128 threads / 32 preds per block => 10 blocks/SM => fine-grained waves (no big tail)
__global__ void __launch_bounds__(128, 10)
k_cost(const float* __restrict__ pc, const float* __restrict__ ps,
       const float* __restrict__ cls,
       const float* __restrict__ gc, const float* __restrict__ gs,
       const void* __restrict__ lab) {
    extern __shared__ unsigned char csm[];
    float4* gp1 = (float4*)csm;                  // lo0, lo1, lo2, gvol
    float4* gp2 = (float4*)(csm + 2048);         // hi0, hi1, hi2, (unused)
    float*  sig_sh = (float*)(csm + 4096);       // [g*33 + p_local], conflict-free
    __shared__ int glab[N_GT];
    __shared__ int is32;
    int tid = threadIdx.x;  // blockDim = 128
    int lane = tid & 31;
    if (blockIdx.x == 0) {
        for (int i = tid; i < NBMW; i += blockDim.x) d_colbm[i] = 0u;
    }
    if (tid == 0) {
        const ull* p8 = (const ull*)lab;
        int f = 0;
        for (int i = 0; i < 64; i++) { if (p8[i] >> 32) { f = 1; break; } }
        is32 = f;
    }
    __syncthreads();
    {
        int t = tid;  // 128 threads cover 128 gts
        long long lv;
        if (is32) lv = (long long)((const int*)lab)[t];
        else      lv = ((const long long*)lab)[t];
        int iv = (int)lv;
        if (iv < 0) iv = 0;
        if (iv >= N_CLS) iv = N_CLS - 1;
        glab[t] = iv;
        float c0 = gc[t*3+0], c1 = gc[t*3+1], c2 = gc[t*3+2];
        float s0 = gs[t*3+0], s1 = gs[t*3+1], s2 = gs[t*3+2];
        float h0s = __fmul_rn(s0, 0.5f), h1s = __fmul_rn(s1, 0.5f), h2s = __fmul_rn(s2, 0.5f);
        float l0 = __fsub_rn(c0, h0s), l1 = __fsub_rn(c1, h1s), l2 = __fsub_rn(c2, h2s);
        float h0 = __fadd_rn(c0, h0s), h1 = __fadd_rn(c1, h1s), h2 = __fadd_rn(c2, h2s);
        float gv = __fmul_rn(__fmul_rn(__fsub_rn(h0,l0), __fsub_rn(h1,l1)), __fsub_rn(h2,l2));
        gp1[t] = make_float4(l0, l1, l2, gv);
        gp2[t] = make_float4(h0, h1, h2, 0.0f);
    }
    __syncthreads();

    // ---- phase A: warp-cooperative sigmoid staging (4 warps, 8 preds each) ----
    {
        int w = tid >> 5;
        for (int pl_ = w; pl_ < COST_PREDS; pl_ += 4) {
            const float* clsrow = cls + ((size_t)(blockIdx.x * COST_PREDS + pl_)) * N_CLS;
            #pragma unroll
            for (int q = 0; q < 4; q++) {
                int g = lane + q * 32;
                float cv = __ldg(clsrow + glab[g]);
                float sig = __fdiv_rn(1.0f, __fadd_rn(1.0f, expf(-cv)));
                sig_sh[g * 33 + pl_] = sig;
            }
        }
    }
    __syncthreads();

    // ---- phase B: matrix + qualifier collection ----
    int pl = tid & 31;                 // pred within block (warp-aligned)
    int p = blockIdx.x * COST_PREDS + pl;
    int gbase = (tid >> 5) * 32;       // 4 quarters of the g-loop
    float c0 = pc[p*3+0], c1 = pc[p*3+1], c2 = pc[p*3+2];
    float s0 = ps[p*3+0], s1 = ps[p*3+1], s2 = ps[p*3+2];
    float h0s = __fmul_rn(s0, 0.5f), h1s = __fmul_rn(s1, 0.5f), h2s = __fmul_rn(s2, 0.5f);
    float pl0 = __fsub_rn(c0, h0s), pl1 = __fsub_rn(c1, h1s), pl2 = __fsub_rn(c2, h2s);
    float ph0 = __fadd_rn(c0, h0s), ph1 = __fadd_rn(c1, h1s), ph2 = __fadd_rn(c2, h2s);
    float vol1 = __fmul_rn(__fmul_rn(__fsub_rn(ph0,pl0), __fsub_rn(ph1,pl1)), __fsub_rn(ph2,pl2));

    #pragma unroll 4
    for (int gi_ = 0; gi_ < 32; gi_++) {
        int g = gbase + gi_;
        float4 A = gp1[g];
        float4 B = gp2[g];
        float d0 = fmaxf(__fsub_rn(fminf(ph0, B.x), fmaxf(pl0, A.x)), 0.f);
        float d1 = fmaxf(__fsub_rn(fminf(ph1, B.y), fmaxf(pl1, A.y)), 0.f);
        float d2 = fmaxf(__fsub_rn(fminf(ph2, B.z), fmaxf(pl2, A.z)), 0.f);
        float ov = __fmul_rn(__fmul_rn(d0, d1), d2);
        float un = fmaxf(__fsub_rn(__fadd_rn(vol1, A.w), ov), GEPS);
        float iou = __fdiv_rn(ov, un);
        float e0 = __fsub_rn(fmaxf(ph0, B.x), fminf(pl0, A.x));
        float e1 = __fsub_rn(fmaxf(ph1, B.y), fminf(pl1, A.y));
        float e2 = __fsub_rn(fmaxf(ph2, B.z), fminf(pl2, A.z));
        float enc = fmaxf(__fmul_rn(__fmul_rn(e0, e1), e2), GEPS);
        float gg = __fsub_rn(iou, __fdiv_rn(__fsub_rn(enc, un), enc));
        float sig = sig_sh[g * 33 + pl];
        d_costm[g][p] = __fadd_rn(-sig, __fmul_rn(-2.0f, gg));

        // warp-aggregated qualifier collection (warp = 32 preds, same g)
        bool q = gg > IOU_THRES;
        unsigned mask = __ballot_sync(0xffffffffu, q);
        if (mask) {
            int leader = __ffs(mask) - 1;
            int base = 0;
            if (lane == leader) base = atomicAdd(&d_gccnt[g], __popc(mask));
            base = __shfl_sync(0xffffffffu, base, leader);
            if (q) {
                int pos = base + __popc(mask & ((1u << lane) - 1u));
                if (pos < GCAP)
                    d_glist[g][pos] = ((ull)(~fkey(gg)) << 32) | (unsigned)p;
            }
        }
    }
}

// ------------------- selection -------------------
// blocks 0..127: cost rows (scan+sample+sort); 128..255: giou rows (list or recompute)
__global__ void k_select(const float* __restrict__ pc, const float* __restrict__ ps,
                         const float* __restrict__ gc, const float* __restrict__ gs) {
    extern __shared__ unsigned char ssm[];
    ull* buf = (ull*)ssm;            // GCAP entries (64KB); aliased as hist in fallbacks
    __shared__ ull samp[512];
    __shared__ int s_cnt, s_c;

    int b = blockIdx.x, tid = threadIdx.x, nth = blockDim.x;  // nth = 512
    unsigned* hist = (unsigned*)buf;

    if (b < N_GT) {
        // ================= cost row =================
        int row = b;
        const float* crow = d_costm[row];
        const float4* crow4 = (const float4*)crow;
        if (tid < 512) {
            float v = crow[tid * 128];
            samp[tid] = ((ull)fkey(v) << 32) | (unsigned)(tid * 128);
        }
        __syncthreads();
        bsort(samp, 512, tid, nth);

        const int slist[5] = {4, 16, 64, 255, 511};
        int si = 0, cc = 0, truecnt = 0;
        while (true) {
            if (tid == 0) s_cnt = 0;
            __syncthreads();
            unsigned Tkey = (unsigned)(samp[slist[si]] >> 32);
            for (int j4 = tid; j4 < N_PRED / 4; j4 += nth) {
                float4 v4 = crow4[j4];
                int j = j4 * 4;
                unsigned k0 = fkey(v4.x), k1 = fkey(v4.y), k2 = fkey(v4.z), k3 = fkey(v4.w);
                if (k0 <= Tkey) { int s = atomicAdd(&s_cnt, 1); if (s < GCAP) buf[s] = ((ull)k0 << 32) | (unsigned)(j+0); }
                if (k1 <= Tkey) { int s = atomicAdd(&s_cnt, 1); if (s < GCAP) buf[s] = ((ull)k1 << 32) | (unsigned)(j+1); }
                if (k2 <= Tkey) { int s = atomicAdd(&s_cnt, 1); if (s < GCAP) buf[s] = ((ull)k2 << 32) | (unsigned)(j+2); }
                if (k3 <= Tkey) { int s = atomicAdd(&s_cnt, 1); if (s < GCAP) buf[s] = ((ull)k3 << 32) | (unsigned)(j+3); }
            }
            __syncthreads();
            truecnt = s_cnt;
            cc = (truecnt < GCAP) ? truecnt : GCAP;
            if (truecnt >= CAND_C && truecnt <= GCAP) break;
            if (truecnt > GCAP) {
                // rare: tie-heavy. exact 2-level 2048-bin histogram.
                for (int i = tid; i < 2048; i += nth) hist[i] = 0;
                __syncthreads();
                for (int j = tid; j < N_PRED; j += nth)
                    atomicAdd(&hist[fkey(crow[j]) >> 21], 1u);
                __syncthreads();
                if (tid == 0) {
                    unsigned need = CAND_C, cum = 0; int bb = 0;
                    for (; bb < 2047; bb++) { if (cum + hist[bb] >= need) break; cum += hist[bb]; }
                    s_c = bb; s_cnt = (int)(need - cum);
                }
                __syncthreads();
                unsigned pfx11 = (unsigned)s_c; int need1 = s_cnt;
                __syncthreads();
                for (int i = tid; i < 2048; i += nth) hist[i] = 0;
                __syncthreads();
                for (int j = tid; j < N_PRED; j += nth) {
                    unsigned k = fkey(crow[j]);
                    if ((k >> 21) == pfx11) atomicAdd(&hist[(k >> 10) & 2047u], 1u);
                }
                __syncthreads();
                if (tid == 0) {
                    unsigned need = (unsigned)need1, cum = 0; int bb = 0;
                    for (; bb < 2047; bb++) { if (cum + hist[bb] >= need) break; cum += hist[bb]; }
                    s_c = (int)((pfx11 << 11) | (unsigned)bb);
                    s_cnt = 0;
                }
                __syncthreads();
                unsigned pfx22 = (unsigned)s_c;
                __syncthreads();
                for (int j = tid; j < N_PRED; j += nth) {
                    unsigned k = fkey(crow[j]);
                    if ((k >> 10) <= pfx22) {
                        int slot = atomicAdd(&s_cnt, 1);
                        if (slot < GCAP) buf[slot] = ((ull)k << 32) | (unsigned)j;
                    }
                }
                __syncthreads();
                truecnt = s_cnt;
                cc = (truecnt < GCAP) ? truecnt : GCAP;
                break;
            }
            si++;
            if (si >= 5) break;
            __syncthreads();
        }
        int n2 = 512; while (n2 < cc) n2 <<= 1;
        for (int i = tid + cc; i < n2; i += nth) buf[i] = 0xFFFFFFFFFFFFFFFFull;
        __syncthreads();
        bsort(buf, n2, tid, nth);
        int keep = (cc < CAND_C) ? cc : CAND_C;
        for (int i = tid; i < keep; i += nth) {
            ull e = buf[i];
            int j = (int)(e & 0xFFFFFFFFull);
            d_ccand_idx[row][i] = j;
            d_ccand_val[row][i] = crow[j];
            atomicOr(&d_colbm[j >> 5], 1u << (j & 31));
        }
        if (tid == 0) d_ccand_cnt[row] = keep;
    } else {
        // ================= giou row =================
        int row = b - N_GT;
        int count = d_gccnt[row];
        int cc;
        if (count <= GCAP) {
            // list path: load collected qualifiers
            const ull* gl = d_glist[row];
            for (int i = tid; i < count; i += nth) buf[i] = gl[i];
            cc = count;
        } else {
            // rare fallback: recompute giou row exactly, exact histogram top-GC_NEED
            float gcx0 = gc[row*3+0], gcx1 = gc[row*3+1], gcx2 = gc[row*3+2];
            float gsx0 = gs[row*3+0], gsx1 = gs[row*3+1], gsx2 = gs[row*3+2];
            float gh0s = __fmul_rn(gsx0,0.5f), gh1s = __fmul_rn(gsx1,0.5f), gh2s = __fmul_rn(gsx2,0.5f);
            float gl0 = __fsub_rn(gcx0,gh0s), gl1 = __fsub_rn(gcx1,gh1s), gl2 = __fsub_rn(gcx2,gh2s);
            float gh0 = __fadd_rn(gcx0,gh0s), gh1 = __fadd_rn(gcx1,gh1s), gh2 = __fadd_rn(gcx2,gh2s);
            float gvol = __fmul_rn(__fmul_rn(__fsub_rn(gh0,gl0), __fsub_rn(gh1,gl1)), __fsub_rn(gh2,gl2));

            for (int i = tid; i < 2048; i += nth) hist[i] = 0;
            __syncthreads();
            for (int j = tid; j < N_PRED; j += nth) {
                float g = giou_of(pc, ps, j, gl0, gl1, gl2, gh0, gh1, gh2, gvol);
                if (g > IOU_THRES) atomicAdd(&hist[(~fkey(g)) >> 21], 1u);
            }
            __syncthreads();
            if (tid == 0) {
                unsigned need = GC_NEED, cum = 0; int bb = 0;
                for (; bb < 2047; bb++) { if (cum + hist[bb] >= need) break; cum += hist[bb]; }
                s_c = bb; s_cnt = (int)(need - cum);
            }
            __syncthreads();
            unsigned pfx11 = (unsigned)s_c; int need1 = s_cnt;
            __syncthreads();
            for (int i = tid; i < 2048; i += nth) hist[i] = 0;
            __syncthreads();
            for (int j = tid; j < N_PRED; j += nth) {
                float g = giou_of(pc, ps, j, gl0, gl1, gl2, gh0, gh1, gh2, gvol);
                if (g > IOU_THRES) {
                    unsigned k = ~fkey(g);
                    if ((k >> 21) == pfx11) atomicAdd(&hist[(k >> 10) & 2047u], 1u);
                }
            }
            __syncthreads();
            if (tid == 0) {
                unsigned need = (unsigned)need1, cum = 0; int bb = 0;
                for (; bb < 2047; bb++) { if (cum + hist[bb] >= need) break; cum += hist[bb]; }
                s_c = (int)((pfx11 << 11) | (unsigned)bb);
                s_cnt = 0;
            }
            __syncthreads();
            unsigned pfx22 = (unsigned)s_c;
            __syncthreads();
            for (int j = tid; j < N_PRED; j += nth) {
                float g = giou_of(pc, ps, j, gl0, gl1, gl2, gh0, gh1, gh2, gvol);
                if (!(g > IOU_THRES)) continue;
                unsigned k = ~fkey(g);
                if ((k >> 10) <= pfx22) {
                    int slot = atomicAdd(&s_cnt, 1);
                    if (slot < GCAP) buf[slot] = ((ull)k << 32) | (unsigned)j;
                }
            }
            __syncthreads();
            cc = (s_cnt < GCAP) ? s_cnt : GCAP;
        }
        __syncthreads();
        int n2 = 512; while (n2 < cc) n2 <<= 1;
        for (int i = tid + cc; i < n2; i += nth) buf[i] = 0xFFFFFFFFFFFFFFFFull;
        __syncthreads();
        bsort(buf, n2, tid, nth);   // key asc == giou desc, idx asc
        int cnt = (cc < GC_NEED) ? cc : GC_NEED;
        for (int i = tid; i < cnt; i += nth)
            d_gcand_idx[row][i] = (int)(buf[i] & 0xFFFFFFFFull);
        if (tid == 0) {
            d_gcand_cnt[row] = cnt;
            d_gccnt[row] = 0;   // reset counter for next graph replay
            // row max = first sorted qualifier; zero-qualifier gts get key 0
            // (they provably precede all qualifying gts; permutation among them
            //  is output-invariant since they emit only (-1,-1) rows)
            d_maxgk[row] = (cc > 0) ? ~((unsigned)(buf[0] >> 32)) : 0u;
        }
    }
}

// ------------------- LSA (slot-based smem state) + dynamic assign + output -----------
__global__ void k_lsa(float* __restrict__ out) {
    extern __shared__ unsigned char dsm[];
    uint16_t* shSlot = (uint16_t*)(dsm + OFF_SLOT);   // cid -> slot (0xFFFF = untouched)
    double*   sDist  = (double*)(dsm + OFF_DIST);
    uint8_t*  sPath  = (uint8_t*)(dsm + OFF_PATH);
    uint16_t* sCol   = (uint16_t*)(dsm + OFF_COL);    // slot -> cid
    unsigned* sSC    = (unsigned*)(dsm + OFF_SC);     // per-slot SC bits
    uint8_t*  shR    = (uint8_t*)(dsm + OFF_R);       // cid -> row (255 = free)
    uint16_t* vslot  = (uint16_t*)(dsm + OFF_VSLOT);  // cid -> v slot (0xFFFF = v==0)
    double*   vval   = (double*)(dsm + OFF_VVAL);
    int*      cbase  = (int*)(dsm + OFF_SLOT);        // alias during prologue only

    __shared__ double u[N_GT];
    __shared__ int SR[N_GT];
    __shared__ int c4r[N_GT];
    __shared__ int pend[N_GT];
    __shared__ int scnt[N_GT];
    __shared__ float s0val[N_GT];
    __shared__ int   s0idx[N_GT];
    __shared__ int   colro[N_GT];
    __shared__ double rv[8];
    __shared__ int rc[8];
    __shared__ int tsum[256];
    __shared__ int s_row, s_sink, s_tcnt, s_vcnt, s_npend, s_nSR;
    __shared__ double s_minval;

    int tid = threadIdx.x, nth = blockDim.x;  // 256
    const double DINF = 1e300;

    // ---- compact scan of column bitmap (cbase aliases shSlot region) ----
    int wbase = tid * 8;
    int cnts8[8]; int ssum = 0;
    #pragma unroll
    for (int w = 0; w < 8; w++) { cnts8[w] = __popc(d_colbm[wbase + w]); ssum += cnts8[w]; }
    tsum[tid] = ssum;
    __syncthreads();
    for (int off = 1; off < 256; off <<= 1) {
        int v_ = 0;
        if (tid >= off) v_ = tsum[tid - off];
        __syncthreads();
        tsum[tid] += v_;
        __syncthreads();
    }
    int excl = tsum[tid] - ssum;
    #pragma unroll
    for (int w = 0; w < 8; w++) { cbase[wbase + w] = excl; excl += cnts8[w]; }
    __syncthreads();
    int nK = tsum[255];
    if (nK > LSA_CAP) nK = LSA_CAP;   // impossible (union <= 16384), safety only

    // ---- remap: build packed (val|cid) candidates + reverse map ----
    for (int x = tid; x < N_GT * CAND_C; x += nth) {
        int row = x >> 7, s = x & 127;
        if (s < d_ccand_cnt[row]) {
            int j = d_ccand_idx[row][s];
            int w = j >> 5;
            int cid = cbase[w] + __popc(d_colbm[w] & ((1u << (j & 31)) - 1u));
            float v_ = d_ccand_val[row][s];
            d_ccpack[row][s] = ((ull)__float_as_uint(v_) << 32) | (unsigned)cid;
            d_rev[cid] = j;
        }
    }
    __syncthreads();   // cbase dead; shSlot region free

    // ---- init smem state ----
    {
        unsigned* p32 = (unsigned*)shSlot;
        for (int i = tid; i < LSA_CAP/2; i += nth) p32[i] = 0xFFFFFFFFu;
        unsigned* q32 = (unsigned*)vslot;
        for (int i = tid; i < LSA_CAP/2; i += nth) q32[i] = 0xFFFFFFFFu;
    }
    for (int i = tid; i < nK; i += nth) shR[i] = 0xFF;
    for (int i = tid; i < SLOT_CAP/32; i += nth) sSC[i] = 0;
    if (tid < N_GT) {
        c4r[tid] = -1;
        scnt[tid] = d_ccand_cnt[tid];
        ull pk = d_ccpack[tid][0];
        s0idx[tid] = (int)(pk & 0xFFFFFFFFull);
        s0val[tid] = __uint_as_float((unsigned)(pk >> 32));
    }
    if (tid == 0) s_vcnt = 0;
    __syncthreads();

    // ---- greedy tight assignment (pure smem, serial) ----
    if (tid == 0) {
        s_npend = 0;
        for (int i = 0; i < N_GT; i++) {
            if (scnt[i] > 0) {
                u[i] = (double)s0val[i];
                int j = s0idx[i];
                if (j >= 0 && j < nK && shR[j] == 0xFF) {
                    shR[j] = (uint8_t)i; c4r[i] = j;
                    continue;
                }
            } else u[i] = 0.0;
            pend[s_npend++] = i;
        }
    }
    __syncthreads();
    int npend = s_npend;

    // ---- block-wide shortest augmenting path per conflicted row ----
    for (int pi = 0; pi < npend; pi++) {
        int cur = pend[pi];
        if (tid == 0) { s_row = cur; s_sink = -1; s_tcnt = 0; s_nSR = 0; s_minval = 0.0; }
        __syncthreads();
        for (int step = 0; step < N_GT; step++) {
            int i = s_row;
            if (tid == 0) SR[s_nSR++] = i;
            double mv0 = s_minval, ui = u[i];
            int cnt = scnt[i];
            for (int s = tid; s < cnt; s += nth) {
                ull pk = d_ccpack[i][s];
                int cid = (int)(pk & 0xFFFFFFFFull);
                int slot = shSlot[cid];
                if (slot != 0xFFFF && ((sSC[slot >> 5] >> (slot & 31)) & 1u)) continue;
                int vs = vslot[cid];
                double v_ = (vs != 0xFFFF) ? vval[vs] : 0.0;
                double r = ((mv0 + (double)__uint_as_float((unsigned)(pk >> 32))) - ui) - v_;
                if (slot == 0xFFFF) {
                    int t2 = atomicAdd(&s_tcnt, 1);
                    if (t2 < SLOT_CAP) {
                        shSlot[cid] = (uint16_t)t2;
                        sCol[t2] = (uint16_t)cid;
                        sDist[t2] = r;
                        sPath[t2] = (uint8_t)i;
                    }
                } else if (r < sDist[slot]) {
                    sDist[slot] = r; sPath[slot] = (uint8_t)i;
                }
            }
            __syncthreads();
            int tcnt = s_tcnt; if (tcnt > SLOT_CAP) tcnt = SLOT_CAP;
            double bv = DINF; int bc = 0x7fffffff;
            for (int t2 = tid; t2 < tcnt; t2 += nth) {
                if ((sSC[t2 >> 5] >> (t2 & 31)) & 1u) continue;
                double sv = sDist[t2];
                int cid = sCol[t2];
                if (sv < bv || (sv == bv && cid < bc)) { bv = sv; bc = cid; }
            }
            #pragma unroll
            for (int off = 16; off > 0; off >>= 1) {
                double ov = __shfl_down_sync(0xffffffffu, bv, off);
                int   oc = __shfl_down_sync(0xffffffffu, bc, off);
                if (ov < bv || (ov == bv && oc < bc)) { bv = ov; bc = oc; }
            }
            if ((tid & 31) == 0) { rv[tid >> 5] = bv; rc[tid >> 5] = bc; }
            __syncthreads();
            if (tid == 0) {
                double fbv = rv[0]; int fbc = rc[0];
                #pragma unroll
                for (int k = 1; k < 8; k++) {
                    if (rv[k] < fbv || (rv[k] == fbv && rc[k] < fbc)) { fbv = rv[k]; fbc = rc[k]; }
                }
                if (fbc >= 0 && fbc < nK) {
                    s_minval = fbv;
                    int slot = shSlot[fbc];
                    sSC[slot >> 5] |= (1u << (slot & 31));
                    int r4 = shR[fbc];
                    if (r4 == 0xFF) s_sink = fbc; else s_row = r4;
                } else s_sink = -2;
            }
            __syncthreads();
            if (s_sink != -1) break;
        }
        if (s_sink >= 0) {
            double mv = s_minval;
            if (tid == 0) {
                u[cur] += mv;
                for (int k = 1; k < s_nSR; k++) {
                    int i2 = SR[k];
                    u[i2] += mv - sDist[shSlot[c4r[i2]]];
                }
            }
            int tcnt = s_tcnt; if (tcnt > SLOT_CAP) tcnt = SLOT_CAP;
            for (int t2 = tid; t2 < tcnt; t2 += nth) {
                if ((sSC[t2 >> 5] >> (t2 & 31)) & 1u) {
                    int cid = sCol[t2];
                    int vs = vslot[cid];
                    if (vs == 0xFFFF) {
                        vs = atomicAdd(&s_vcnt, 1);
                        if (vs < VV_CAP) { vslot[cid] = (uint16_t)vs; vval[vs] = 0.0; }
                    }
                    if (vs < VV_CAP) vval[vs] -= mv - sDist[t2];
                }
            }
            __syncthreads();
            if (tid == 0) {
                int j = s_sink;
                for (int it = 0; it <= N_GT && j >= 0; it++) {
                    int i2 = sPath[shSlot[j]];
                    shR[j] = (uint8_t)i2;
                    int tmp = c4r[i2];
                    c4r[i2] = j;
                    j = tmp;
                    if (i2 == cur) break;
                }
            }
        }
        __syncthreads();
        // reset only the touched entries
        {
            int tw = (s_tcnt < SLOT_CAP ? s_tcnt : SLOT_CAP);
            for (int t2 = tid; t2 < tw; t2 += nth) shSlot[sCol[t2]] = 0xFFFF;
            for (int i = tid; i < (tw + 31) / 32; i += nth) sSC[i] = 0;
        }
        __syncthreads();
    }
    if (tid < N_GT) colro[tid] = (c4r[tid] >= 0) ? d_rev[c4r[tid]] : -1;
    __syncthreads();

    // ================= dynamic assignment phase (reuses dead dsm region) =================
    unsigned* used = (unsigned*)dsm;                    // 8KB @ 0
    int* res_p = (int*)(dsm + 8192);                    // 5632B
    int* res_g = (int*)(dsm + 13824);                   // 5632B
    int* pref  = (int*)(dsm + 19456);                   // 16KB: pref[g*32+s], depth 32
    int* gcnts = (int*)(dsm + 35840);                   // 512B
    int* ordv  = (int*)(dsm + 36352);                   // 512B
    unsigned* mgk = (unsigned*)(dsm + 36864);           // 512B

    for (int i = tid; i < NBMW; i += nth) used[i] = 0;
    if (tid < N_GT) { gcnts[tid] = d_gcand_cnt[tid]; mgk[tid] = d_maxgk[tid]; }
    __syncthreads();
    // stable ascending argsort of maxg keys (fkey monotonic => same order as floats)
    if (tid < N_GT) {
        unsigned mv = mgk[tid]; int r = 0;
        for (int j = 0; j < N_GT; j++) {
            unsigned o = mgk[j];
            if (o < mv || (o == mv && j < tid)) r++;
        }
        ordv[r] = tid;
    }
    for (int i = tid; i < N_GT * 32; i += nth) {
        int g = i >> 5, s = i & 31;
        pref[i] = (s < gcnts[g]) ? d_gcand_idx[g][s] : -1;
    }
    if (tid < N_GT) {
        int p = colro[tid];
        if (p >= 0 && p < N_PRED) atomicOr(&used[p >> 5], 1u << (p & 31));
        res_p[tid] = p;
        res_g[tid] = tid;
    }
    __syncthreads();
    if (tid < 32) {
        int lane = tid;
        for (int t = 0; t < N_GT; t++) {
            int g = ordv[t];
            int cnt = gcnts[g];
            int picked = 0;
            for (int base = 0; base < cnt && picked < MAX_DYN; base += 32) {
                int idx = -1;
                if (base + lane < cnt)
                    idx = (base == 0) ? pref[g * 32 + lane] : d_gcand_idx[g][base + lane];
                bool elig = (idx >= 0) && (idx < N_PRED) && !((used[idx >> 5] >> (idx & 31)) & 1u);
                unsigned m = __ballot_sync(0xffffffffu, elig);
                int K = MAX_DYN - picked;
                int pre = __popc(m & ((1u << lane) - 1u));
                if (elig && pre < K) {
                    atomicOr(&used[idx >> 5], 1u << (idx & 31));
                    res_p[128 + t * MAX_DYN + picked + pre] = idx;
                    res_g[128 + t * MAX_DYN + picked + pre] = g;
                }
                int got = __popc(m); if (got > K) got = K;
                picked += got;
                __syncwarp();
            }
            if (lane >= picked && lane < MAX_DYN) {
                res_p[128 + t * MAX_DYN + lane] = -1;
                res_g[128 + t * MAX_DYN + lane] = -1;
            }
            __syncwarp();
        }
    }
    __syncthreads();
    for (int i = tid; i < 1408; i += nth) {
        out[i]        = (float)res_p[i];
        out[1408 + i] = (float)res_g[i];
    }
}

// ------------------- launch (inputs resolved by element count) -------------------
extern "C" void kernel_launch(void* const* d_in, const int* in_sizes, int n_in,
                              void* d_out, int out_size) {
    const float* all_centers = 0;
    const float* all_sizes   = 0;
    const float* all_cls     = 0;
    const float* gt_centers  = 0;
    const float* gt_sizes    = 0;
    const void*  gt_labels   = 0;
    int seen196 = 0, seen384 = 0;
    for (int i = 0; i < n_in; i++) {
        long long s = in_sizes[i];
        if (s == (long long)N_PRED * N_CLS) {
            all_cls = (const float*)d_in[i];
        } else if (s == (long long)N_PRED * 3) {
            if (seen196++ == 0) all_centers = (const float*)d_in[i];
            else                all_sizes   = (const float*)d_in[i];
        } else if (s == (long long)N_GT * 3) {
            if (seen384++ == 0) gt_centers = (const float*)d_in[i];
            else                gt_sizes   = (const float*)d_in[i];
        } else if (s == (long long)N_GT) {
            gt_labels = d_in[i];
        }
    }

    cudaFuncSetAttribute(k_cost, cudaFuncAttributeMaxDynamicSharedMemorySize, COST_DYN_BYTES);
    cudaFuncSetAttribute(k_select, cudaFuncAttributeMaxDynamicSharedMemorySize, SEL_DYN_BYTES);
    cudaFuncSetAttribute(k_lsa, cudaFuncAttributeMaxDynamicSharedMemorySize, LSA_DYN_BYTES);

    k_cost<<<N_PRED / COST_PREDS, 128, COST_DYN_BYTES>>>(all_centers, all_sizes, all_cls,
                                                         gt_centers, gt_sizes, gt_labels);
    k_select<<<2 * N_GT, 512, SEL_DYN_BYTES>>>(all_centers, all_sizes, gt_centers, gt_sizes);
    k_lsa<<<1, 256, LSA_DYN_BYTES>>>((float*)d_out);
}